// round 3
// baseline (speedup 1.0000x reference)
#include <cuda_runtime.h>
#include <math.h>

#define BATCH 16
#define SEQ   2048
#define HDIM  128
#define DDIM  64

// ---------------- device scratch (no allocations allowed) ----------------
__device__ float g_E[(size_t)BATCH * SEQ * SEQ];   // exp(scores), [b][q][k], 256 MB
__device__ float g_Qt[BATCH * DDIM * SEQ];         // Q transposed [b][d][s], pre-scaled 1/8
__device__ float g_Kt[BATCH * DDIM * SEQ];         // K transposed [b][d][s]
__device__ float g_PE[SEQ * HDIM];                 // sinusoidal PE table
__device__ float g_w[BATCH * SEQ];                 // V[b,k,:]·Wf
__device__ float g_Z[BATCH * SEQ];                 // column sums of exp(scores)
__device__ float g_c[BATCH * SEQ];                 // w / Z
__device__ float g_wvf[HDIM];                      // Wv @ Wf  (fold V proj + final proj)

// ---------------- PE table ----------------
__global__ void k_pe() {
    int idx = blockIdx.x * 256 + threadIdx.x;
    if (idx >= SEQ * HDIM) return;
    int s = idx / HDIM, h = idx % HDIM;
    double denom = pow(10000.0, (double)(h & ~1) / 128.0);
    float ang = (float)((double)s / denom);
    g_PE[idx] = (h & 1) ? cosf(ang) : sinf(ang);
}

// ---------------- wvf[h] = sum_d Wv[h][d] * Wf[d] ----------------
__global__ void k_wvf(const float* __restrict__ Wv, const float* __restrict__ Wf) {
    int h = threadIdx.x;  // 128 threads
    float acc = 0.f;
#pragma unroll 16
    for (int d = 0; d < DDIM; d++) acc += Wv[h * DDIM + d] * Wf[d];
    g_wvf[h] = acc;
}

// ---------------- w[b,s] = (x[b,s,:] + PE[s,:]) · wvf ----------------
__global__ void k_rowdot(const float* __restrict__ x) {
    int row  = blockIdx.x * 8 + (threadIdx.x >> 5);  // global row in [0, B*S)
    int lane = threadIdx.x & 31;
    int s = row & (SEQ - 1);
    const float4* xr = (const float4*)(x + (size_t)row * HDIM);
    const float4* pe = (const float4*)(g_PE + (size_t)s * HDIM);
    const float4* wv = (const float4*)g_wvf;
    float4 xv = xr[lane], pv = pe[lane], wf = wv[lane];
    float acc = (xv.x + pv.x) * wf.x + (xv.y + pv.y) * wf.y +
                (xv.z + pv.z) * wf.z + (xv.w + pv.w) * wf.w;
#pragma unroll
    for (int off = 16; off; off >>= 1) acc += __shfl_xor_sync(0xFFFFFFFFu, acc, off);
    if (lane == 0) g_w[row] = acc;
}

// ---------------- projection: xp @ [Wq | Wk] -> Qt (scaled 1/8), Kt ----------------
__global__ void __launch_bounds__(256) k_proj(const float* __restrict__ x,
                                              const float* __restrict__ Wq,
                                              const float* __restrict__ Wk) {
    extern __shared__ float sm[];
    float* As = sm;                // [128][128]  As[h][s_loc]  (xp, transposed)
    float* Ws = sm + 128 * 128;    // [128][128]  Ws[h][n]  n<64: Wq, n>=64: Wk
    int b = blockIdx.y, s0 = blockIdx.x * 128;
    int tid = threadIdx.x;

    // load weights (8192 floats each = 2048 float4)
    const float4* wq4 = (const float4*)Wq;
    const float4* wk4 = (const float4*)Wk;
    for (int i = tid; i < 2048; i += 256) {
        int h = i >> 4, c4 = i & 15;          // 16 float4 per 64-float row
        ((float4*)(Ws + h * 128))[c4]      = wq4[i];
        ((float4*)(Ws + h * 128 + 64))[c4] = wk4[i];
    }
    // load x tile + PE, transpose into As[h][s]
    for (int i = tid; i < 4096; i += 256) {
        int sl = i >> 5, h4 = (i & 31) * 4;
        float4 xv = *(const float4*)(x + ((size_t)(b * SEQ + s0 + sl)) * HDIM + h4);
        float4 pv = *(const float4*)(g_PE + (size_t)(s0 + sl) * HDIM + h4);
        As[(h4 + 0) * 128 + sl] = xv.x + pv.x;
        As[(h4 + 1) * 128 + sl] = xv.y + pv.y;
        As[(h4 + 2) * 128 + sl] = xv.z + pv.z;
        As[(h4 + 3) * 128 + sl] = xv.w + pv.w;
    }
    __syncthreads();

    int tx = tid & 15, ty = tid >> 4;
    float acc[8][8];
#pragma unroll
    for (int i = 0; i < 8; i++)
#pragma unroll
        for (int j = 0; j < 8; j++) acc[i][j] = 0.f;

#pragma unroll 8
    for (int h = 0; h < 128; h++) {
        float a[8], bb[8];
        *(float4*)(a)      = *(float4*)(As + h * 128 + ty * 4);
        *(float4*)(a + 4)  = *(float4*)(As + h * 128 + 64 + ty * 4);
        *(float4*)(bb)     = *(float4*)(Ws + h * 128 + tx * 4);
        *(float4*)(bb + 4) = *(float4*)(Ws + h * 128 + 64 + tx * 4);
#pragma unroll
        for (int i = 0; i < 8; i++)
#pragma unroll
            for (int j = 0; j < 8; j++) acc[i][j] += a[i] * bb[j];
    }

    // write Qt (cols j<4 -> d = tx*4+j, scaled 1/8) and Kt (cols j>=4)
#pragma unroll
    for (int j = 0; j < 4; j++) {
        int d = tx * 4 + j;
        float4 q0 = make_float4(.125f * acc[0][j], .125f * acc[1][j],
                                .125f * acc[2][j], .125f * acc[3][j]);
        float4 q1 = make_float4(.125f * acc[4][j], .125f * acc[5][j],
                                .125f * acc[6][j], .125f * acc[7][j]);
        *(float4*)(g_Qt + (size_t)(b * DDIM + d) * SEQ + s0 + ty * 4)      = q0;
        *(float4*)(g_Qt + (size_t)(b * DDIM + d) * SEQ + s0 + 64 + ty * 4) = q1;
        float4 k0 = make_float4(acc[0][j + 4], acc[1][j + 4], acc[2][j + 4], acc[3][j + 4]);
        float4 k1 = make_float4(acc[4][j + 4], acc[5][j + 4], acc[6][j + 4], acc[7][j + 4]);
        *(float4*)(g_Kt + (size_t)(b * DDIM + d) * SEQ + s0 + ty * 4)      = k0;
        *(float4*)(g_Kt + (size_t)(b * DDIM + d) * SEQ + s0 + 64 + ty * 4) = k1;
    }
}

// ---------------- scores: E = exp(Q K^T / 8), Z = column sums over q ----------------
__global__ void __launch_bounds__(256, 2) k_scores() {
    extern __shared__ float sm[];
    float* Bs  = sm;                 // K tile [64][128]   Bs[d][k_loc]
    float* As  = sm + 64 * 128;      // Q tile [64][128]   As[d][q_loc]
    float* red = sm + 2 * 64 * 128;  // [16][128] column-sum reduction

    int b = blockIdx.y, k0 = blockIdx.x * 128;
    int tid = threadIdx.x, tx = tid & 15, ty = tid >> 4;

    // load K tile once (resident for the whole q loop)
    for (int i = tid; i < 2048; i += 256) {
        int d = i >> 5, c4 = i & 31;
        ((float4*)(Bs + d * 128))[c4] =
            ((const float4*)(g_Kt + (size_t)(b * DDIM + d) * SEQ + k0))[c4];
    }

    float csum[8];
#pragma unroll
    for (int j = 0; j < 8; j++) csum[j] = 0.f;

    for (int q0 = 0; q0 < SEQ; q0 += 128) {
        __syncthreads();  // protect As from previous iteration
        for (int i = tid; i < 2048; i += 256) {
            int d = i >> 5, c4 = i & 31;
            ((float4*)(As + d * 128))[c4] =
                ((const float4*)(g_Qt + (size_t)(b * DDIM + d) * SEQ + q0))[c4];
        }
        __syncthreads();

        float acc[8][8];
#pragma unroll
        for (int i = 0; i < 8; i++)
#pragma unroll
            for (int j = 0; j < 8; j++) acc[i][j] = 0.f;

#pragma unroll 8
        for (int d = 0; d < DDIM; d++) {
            float a[8], bb[8];
            *(float4*)(a)      = *(float4*)(As + d * 128 + ty * 4);
            *(float4*)(a + 4)  = *(float4*)(As + d * 128 + 64 + ty * 4);
            *(float4*)(bb)     = *(float4*)(Bs + d * 128 + tx * 4);
            *(float4*)(bb + 4) = *(float4*)(Bs + d * 128 + 64 + tx * 4);
#pragma unroll
            for (int i = 0; i < 8; i++)
#pragma unroll
                for (int j = 0; j < 8; j++) acc[i][j] += a[i] * bb[j];
        }

        // exp, streaming store, column-sum accumulate (fixed order -> deterministic)
        size_t base = (size_t)b * SEQ * SEQ;
#pragma unroll
        for (int i = 0; i < 8; i++) {
            int q = q0 + ty * 4 + (i & 3) + 64 * (i >> 2);
            float e[8];
#pragma unroll
            for (int j = 0; j < 8; j++) {
                e[j] = __expf(acc[i][j]);
                csum[j] += e[j];
            }
            *(float4*)(g_E + base + (size_t)q * SEQ + k0 + tx * 4) =
                make_float4(e[0], e[1], e[2], e[3]);
            *(float4*)(g_E + base + (size_t)q * SEQ + k0 + 64 + tx * 4) =
                make_float4(e[4], e[5], e[6], e[7]);
        }
    }

    // reduce column sums across ty
    __syncthreads();
#pragma unroll
    for (int j = 0; j < 8; j++) {
        int col = tx * 4 + (j & 3) + 64 * (j >> 2);
        red[ty * 128 + col] = csum[j];
    }
    __syncthreads();
    if (tid < 128) {
        float z = 0.f;
#pragma unroll
        for (int t = 0; t < 16; t++) z += red[t * 128 + tid];
        g_Z[b * SEQ + k0 + tid] = z;
    }
}

// ---------------- c = w / Z ----------------
__global__ void k_div() {
    int i = blockIdx.x * 256 + threadIdx.x;
    g_c[i] = g_w[i] / g_Z[i];
}

// ---------------- out[b,q] = bf + E[b,q,:] · c[b,:] ----------------
__global__ void __launch_bounds__(256) k_out(const float* __restrict__ bf,
                                             float* __restrict__ out) {
    __shared__ float cs[SEQ];
    int b = blockIdx.y, q0 = blockIdx.x * 8;
    int tid = threadIdx.x;
    for (int i = tid; i < SEQ; i += 256) cs[i] = g_c[b * SEQ + i];
    __syncthreads();
    int w = tid >> 5, lane = tid & 31;
    int q = q0 + w;
    const float4* E4 = (const float4*)(g_E + ((size_t)(b * SEQ + q)) * SEQ);
    const float4* c4 = (const float4*)cs;
    float acc = 0.f;
#pragma unroll 4
    for (int i = lane; i < SEQ / 4; i += 32) {
        float4 e = E4[i];
        float4 c = c4[i];
        acc += e.x * c.x + e.y * c.y + e.z * c.z + e.w * c.w;
    }
#pragma unroll
    for (int off = 16; off; off >>= 1) acc += __shfl_xor_sync(0xFFFFFFFFu, acc, off);
    if (lane == 0) out[b * SEQ + q] = acc + bf[0];
}

// ---------------- launch ----------------
extern "C" void kernel_launch(void* const* d_in, const int* in_sizes, int n_in,
                              void* d_out, int out_size) {
    const float* x  = (const float*)d_in[0];
    const float* Wq = (const float*)d_in[1];
    const float* Wk = (const float*)d_in[2];
    const float* Wv = (const float*)d_in[3];
    const float* Wf = (const float*)d_in[4];
    const float* bf = (const float*)d_in[5];
    float* out = (float*)d_out;

    cudaFuncSetAttribute(k_proj,   cudaFuncAttributeMaxDynamicSharedMemorySize, 128 * 1024);
    cudaFuncSetAttribute(k_scores, cudaFuncAttributeMaxDynamicSharedMemorySize, 72 * 1024);

    k_pe<<<(SEQ * HDIM + 255) / 256, 256>>>();
    k_wvf<<<1, 128>>>(Wv, Wf);
    k_rowdot<<<(BATCH * SEQ) / 8, 256>>>(x);
    k_proj<<<dim3(SEQ / 128, BATCH), 256, 128 * 1024>>>(x, Wq, Wk);
    k_scores<<<dim3(SEQ / 128, BATCH), 256, 72 * 1024>>>();
    k_div<<<(BATCH * SEQ) / 256, 256>>>();
    k_out<<<dim3(SEQ / 8, BATCH), 256>>>(bf, out);
}

// round 6
// speedup vs baseline: 1.0054x; 1.0054x over previous
#include <cuda_runtime.h>
#include <math.h>

#define BATCH 16
#define SEQ   2048
#define HDIM  128
#define DDIM  64

typedef unsigned long long u64;

// packed f32x2 FMA: d = a*b + c (elementwise on 2 fp32 lanes) — sm_100+ only
__device__ __forceinline__ u64 ffma2(u64 a, u64 b, u64 c) {
    u64 d;
    asm("fma.rn.f32x2 %0, %1, %2, %3;" : "=l"(d) : "l"(a), "l"(b), "l"(c));
    return d;
}
// broadcast one fp32 into both lanes of a 64-bit f32x2 reg
__device__ __forceinline__ u64 dup2(float x) {
    u64 d;
    asm("mov.b64 %0, {%1, %1};" : "=l"(d) : "f"(x));
    return d;
}
__device__ __forceinline__ float2 unpack2(u64 v) {
    float2 f;
    asm("mov.b64 {%0, %1}, %2;" : "=f"(f.x), "=f"(f.y) : "l"(v));
    return f;
}

// ---------------- device scratch (no allocations allowed) ----------------
__device__ float g_E[(size_t)BATCH * SEQ * SEQ];   // exp(scores), [b][q][k], 256 MB
__device__ float g_Qt[BATCH * DDIM * SEQ];         // Q transposed [b][d][s], pre-scaled 1/8
__device__ float g_Kt[BATCH * DDIM * SEQ];         // K transposed [b][d][s]
__device__ float g_PE[SEQ * HDIM];                 // sinusoidal PE table
__device__ float g_w[BATCH * SEQ];                 // V[b,k,:]·Wf
__device__ float g_Z[BATCH * SEQ];                 // column sums of exp(scores)
__device__ float g_c[BATCH * SEQ];                 // w / Z
__device__ float g_wvf[HDIM];                      // Wv @ Wf  (fold V proj + final proj)

// ---------------- PE table ----------------
__global__ void k_pe() {
    int idx = blockIdx.x * 256 + threadIdx.x;
    if (idx >= SEQ * HDIM) return;
    int s = idx / HDIM, h = idx % HDIM;
    double denom = pow(10000.0, (double)(h & ~1) / 128.0);
    float ang = (float)((double)s / denom);
    g_PE[idx] = (h & 1) ? cosf(ang) : sinf(ang);
}

// ---------------- wvf[h] = sum_d Wv[h][d] * Wf[d] ----------------
__global__ void k_wvf(const float* __restrict__ Wv, const float* __restrict__ Wf) {
    int h = threadIdx.x;  // 128 threads
    float acc = 0.f;
#pragma unroll 16
    for (int d = 0; d < DDIM; d++) acc += Wv[h * DDIM + d] * Wf[d];
    g_wvf[h] = acc;
}

// ---------------- w[b,s] = (x[b,s,:] + PE[s,:]) · wvf ----------------
__global__ void k_rowdot(const float* __restrict__ x) {
    int row  = blockIdx.x * 8 + (threadIdx.x >> 5);  // global row in [0, B*S)
    int lane = threadIdx.x & 31;
    int s = row & (SEQ - 1);
    const float4* xr = (const float4*)(x + (size_t)row * HDIM);
    const float4* pe = (const float4*)(g_PE + (size_t)s * HDIM);
    const float4* wv = (const float4*)g_wvf;
    float4 xv = xr[lane], pv = pe[lane], wf = wv[lane];
    float acc = (xv.x + pv.x) * wf.x + (xv.y + pv.y) * wf.y +
                (xv.z + pv.z) * wf.z + (xv.w + pv.w) * wf.w;
#pragma unroll
    for (int off = 16; off; off >>= 1) acc += __shfl_xor_sync(0xFFFFFFFFu, acc, off);
    if (lane == 0) g_w[row] = acc;
}

// ---------------- projection: xp @ [Wq | Wk] -> Qt (scaled 1/8), Kt ----------------
__global__ void __launch_bounds__(256) k_proj(const float* __restrict__ x,
                                              const float* __restrict__ Wq,
                                              const float* __restrict__ Wk) {
    extern __shared__ float sm[];
    float* As = sm;                // [128][128]  As[h][s_loc]  (xp, transposed)
    float* Ws = sm + 128 * 128;    // [128][128]  Ws[h][n]  n<64: Wq, n>=64: Wk
    int b = blockIdx.y, s0 = blockIdx.x * 128;
    int tid = threadIdx.x;

    // load weights (8192 floats each = 2048 float4)
    const float4* wq4 = (const float4*)Wq;
    const float4* wk4 = (const float4*)Wk;
    for (int i = tid; i < 2048; i += 256) {
        int h = i >> 4, c4 = i & 15;          // 16 float4 per 64-float row
        ((float4*)(Ws + h * 128))[c4]      = wq4[i];
        ((float4*)(Ws + h * 128 + 64))[c4] = wk4[i];
    }
    // load x tile + PE, transpose into As[h][s]
    for (int i = tid; i < 4096; i += 256) {
        int sl = i >> 5, h4 = (i & 31) * 4;
        float4 xv = *(const float4*)(x + ((size_t)(b * SEQ + s0 + sl)) * HDIM + h4);
        float4 pv = *(const float4*)(g_PE + (size_t)(s0 + sl) * HDIM + h4);
        As[(h4 + 0) * 128 + sl] = xv.x + pv.x;
        As[(h4 + 1) * 128 + sl] = xv.y + pv.y;
        As[(h4 + 2) * 128 + sl] = xv.z + pv.z;
        As[(h4 + 3) * 128 + sl] = xv.w + pv.w;
    }
    __syncthreads();

    int tx = tid & 15, ty = tid >> 4;
    // acc2[i][j2]: packed pair = (acc[i][2*j2], acc[i][2*j2+1]); j2 0..1 -> Wq cols, 2..3 -> Wk cols
    u64 acc2[8][4];
#pragma unroll
    for (int i = 0; i < 8; i++)
#pragma unroll
        for (int j = 0; j < 4; j++) acc2[i][j] = 0ull;

#pragma unroll 8
    for (int h = 0; h < 128; h++) {
        float a[8];
        *(float4*)(a)      = *(float4*)(As + h * 128 + ty * 4);
        *(float4*)(a + 4)  = *(float4*)(As + h * 128 + 64 + ty * 4);
        ulonglong2 bq = *(const ulonglong2*)(Ws + h * 128 + tx * 4);       // (b0,b1),(b2,b3)
        ulonglong2 bk = *(const ulonglong2*)(Ws + h * 128 + 64 + tx * 4);  // (b4,b5),(b6,b7)
        u64 b2[4] = {bq.x, bq.y, bk.x, bk.y};
#pragma unroll
        for (int i = 0; i < 8; i++) {
            u64 ad = dup2(a[i]);
#pragma unroll
            for (int j = 0; j < 4; j++) acc2[i][j] = ffma2(ad, b2[j], acc2[i][j]);
        }
    }

    // unpack & write Qt (scaled 1/8) and Kt
#pragma unroll
    for (int j2 = 0; j2 < 2; j2++) {
#pragma unroll
        for (int h = 0; h < 2; h++) {
            int d = tx * 4 + j2 * 2 + h;
            float q[8], k[8];
#pragma unroll
            for (int i = 0; i < 8; i++) {
                float2 fq = unpack2(acc2[i][j2]);
                float2 fk = unpack2(acc2[i][j2 + 2]);
                q[i] = .125f * (h ? fq.y : fq.x);
                k[i] = (h ? fk.y : fk.x);
            }
            *(float4*)(g_Qt + (size_t)(b * DDIM + d) * SEQ + s0 + ty * 4)      = *(float4*)(q);
            *(float4*)(g_Qt + (size_t)(b * DDIM + d) * SEQ + s0 + 64 + ty * 4) = *(float4*)(q + 4);
            *(float4*)(g_Kt + (size_t)(b * DDIM + d) * SEQ + s0 + ty * 4)      = *(float4*)(k);
            *(float4*)(g_Kt + (size_t)(b * DDIM + d) * SEQ + s0 + 64 + ty * 4) = *(float4*)(k + 4);
        }
    }
}

// ---------------- scores: E = exp(Q K^T / 8), Z = column sums over q ----------------
__global__ void __launch_bounds__(256, 2) k_scores() {
    extern __shared__ float sm[];
    float* Bs  = sm;                 // K tile [64][128]   Bs[d][k_loc]
    float* As  = sm + 64 * 128;      // Q tile [64][128]   As[d][q_loc]
    float* red = sm + 2 * 64 * 128;  // [16][128] column-sum reduction

    int b = blockIdx.y, k0 = blockIdx.x * 128;
    int tid = threadIdx.x, tx = tid & 15, ty = tid >> 4;

    // load K tile once (resident for the whole q loop)
    for (int i = tid; i < 2048; i += 256) {
        int d = i >> 5, c4 = i & 31;
        ((float4*)(Bs + d * 128))[c4] =
            ((const float4*)(g_Kt + (size_t)(b * DDIM + d) * SEQ + k0))[c4];
    }

    float csum[8];
#pragma unroll
    for (int j = 0; j < 8; j++) csum[j] = 0.f;

    for (int q0 = 0; q0 < SEQ; q0 += 128) {
        __syncthreads();  // protect As from previous iteration
        for (int i = tid; i < 2048; i += 256) {
            int d = i >> 5, c4 = i & 31;
            ((float4*)(As + d * 128))[c4] =
                ((const float4*)(g_Qt + (size_t)(b * DDIM + d) * SEQ + q0))[c4];
        }
        __syncthreads();

        // acc2[i][j2]: packed pair along k; j2 0..1 -> cols k0+tx*4+{0..3}, j2 2..3 -> k0+64+tx*4+{0..3}
        u64 acc2[8][4];
#pragma unroll
        for (int i = 0; i < 8; i++)
#pragma unroll
            for (int j = 0; j < 4; j++) acc2[i][j] = 0ull;

#pragma unroll 8
        for (int d = 0; d < DDIM; d++) {
            float a[8];
            *(float4*)(a)      = *(float4*)(As + d * 128 + ty * 4);
            *(float4*)(a + 4)  = *(float4*)(As + d * 128 + 64 + ty * 4);
            ulonglong2 b0 = *(const ulonglong2*)(Bs + d * 128 + tx * 4);
            ulonglong2 b1 = *(const ulonglong2*)(Bs + d * 128 + 64 + tx * 4);
            u64 b2[4] = {b0.x, b0.y, b1.x, b1.y};
#pragma unroll
            for (int i = 0; i < 8; i++) {
                u64 ad = dup2(a[i]);
#pragma unroll
                for (int j = 0; j < 4; j++) acc2[i][j] = ffma2(ad, b2[j], acc2[i][j]);
            }
        }

        // exp, streaming store, column-sum accumulate (fixed order -> deterministic)
        size_t base = (size_t)b * SEQ * SEQ;
#pragma unroll
        for (int i = 0; i < 8; i++) {
            int q = q0 + ty * 4 + (i & 3) + 64 * (i >> 2);
            float e[8];
#pragma unroll
            for (int j2 = 0; j2 < 4; j2++) {
                float2 f = unpack2(acc2[i][j2]);
                e[j2 * 2 + 0] = __expf(f.x);
                e[j2 * 2 + 1] = __expf(f.y);
            }
#pragma unroll
            for (int j = 0; j < 8; j++) csum[j] += e[j];
            *(float4*)(g_E + base + (size_t)q * SEQ + k0 + tx * 4) =
                make_float4(e[0], e[1], e[2], e[3]);
            *(float4*)(g_E + base + (size_t)q * SEQ + k0 + 64 + tx * 4) =
                make_float4(e[4], e[5], e[6], e[7]);
        }
    }

    // reduce column sums across ty; csum[j]: j 0..3 -> col tx*4+j, 4..7 -> 64+tx*4+(j-4)
    __syncthreads();
#pragma unroll
    for (int j = 0; j < 8; j++) {
        int col = tx * 4 + (j & 3) + 64 * (j >> 2);
        red[ty * 128 + col] = csum[j];
    }
    __syncthreads();
    if (tid < 128) {
        float z = 0.f;
#pragma unroll
        for (int t = 0; t < 16; t++) z += red[t * 128 + tid];
        g_Z[b * SEQ + k0 + tid] = z;
    }
}

// ---------------- c = w / Z ----------------
__global__ void k_div() {
    int i = blockIdx.x * 256 + threadIdx.x;
    g_c[i] = g_w[i] / g_Z[i];
}

// ---------------- out[b,q] = bf + E[b,q,:] · c[b,:] ----------------
__global__ void __launch_bounds__(256) k_out(const float* __restrict__ bf,
                                             float* __restrict__ out) {
    __shared__ float cs[SEQ];
    int b = blockIdx.y, q0 = blockIdx.x * 8;
    int tid = threadIdx.x;
    for (int i = tid; i < SEQ; i += 256) cs[i] = g_c[b * SEQ + i];
    __syncthreads();
    int w = tid >> 5, lane = tid & 31;
    int q = q0 + w;
    const float4* E4 = (const float4*)(g_E + ((size_t)(b * SEQ + q)) * SEQ);
    const float4* c4 = (const float4*)cs;
    float acc = 0.f;
#pragma unroll 4
    for (int i = lane; i < SEQ / 4; i += 32) {
        float4 e = E4[i];
        float4 c = c4[i];
        acc += e.x * c.x + e.y * c.y + e.z * c.z + e.w * c.w;
    }
#pragma unroll
    for (int off = 16; off; off >>= 1) acc += __shfl_xor_sync(0xFFFFFFFFu, acc, off);
    if (lane == 0) out[b * SEQ + q] = acc + bf[0];
}

// ---------------- launch ----------------
extern "C" void kernel_launch(void* const* d_in, const int* in_sizes, int n_in,
                              void* d_out, int out_size) {
    const float* x  = (const float*)d_in[0];
    const float* Wq = (const float*)d_in[1];
    const float* Wk = (const float*)d_in[2];
    const float* Wv = (const float*)d_in[3];
    const float* Wf = (const float*)d_in[4];
    const float* bf = (const float*)d_in[5];
    float* out = (float*)d_out;

    cudaFuncSetAttribute(k_proj,   cudaFuncAttributeMaxDynamicSharedMemorySize, 128 * 1024);
    cudaFuncSetAttribute(k_scores, cudaFuncAttributeMaxDynamicSharedMemorySize, 72 * 1024);

    k_pe<<<(SEQ * HDIM + 255) / 256, 256>>>();
    k_wvf<<<1, 128>>>(Wv, Wf);
    k_rowdot<<<(BATCH * SEQ) / 8, 256>>>(x);
    k_proj<<<dim3(SEQ / 128, BATCH), 256, 128 * 1024>>>(x, Wq, Wk);
    k_scores<<<dim3(SEQ / 128, BATCH), 256, 72 * 1024>>>();
    k_div<<<(BATCH * SEQ) / 256, 256>>>();
    k_out<<<dim3(SEQ / 8, BATCH), 256>>>(bf, out);
}

// round 10
// speedup vs baseline: 1.5972x; 1.5887x over previous
#include <cuda_runtime.h>
#include <cuda_bf16.h>
#include <cuda_fp16.h>
#include <math.h>
#include <stdint.h>

#define BATCH 16
#define SEQ   2048
#define HDIM  128
#define DDIM  64

typedef unsigned long long u64;
typedef unsigned int u32;

// ======================= small helpers =======================
__device__ __forceinline__ u64 ffma2(u64 a, u64 b, u64 c) {
    u64 d;
    asm("fma.rn.f32x2 %0, %1, %2, %3;" : "=l"(d) : "l"(a), "l"(b), "l"(c));
    return d;
}
__device__ __forceinline__ u64 dup2(float x) {
    u64 d;
    asm("mov.b64 %0, {%1, %1};" : "=l"(d) : "f"(x));
    return d;
}
__device__ __forceinline__ float2 unpack2(u64 v) {
    float2 f;
    asm("mov.b64 {%0, %1}, %2;" : "=f"(f.x), "=f"(f.y) : "l"(v));
    return f;
}
// split (x,y) into packed bf16x2 hi and lo words (low half = x)
__device__ __forceinline__ void split2(float x, float y, u32& hi, u32& lo) {
    __nv_bfloat16 hx = __float2bfloat16(x);
    __nv_bfloat16 hy = __float2bfloat16(y);
    __nv_bfloat16 lx = __float2bfloat16(x - __bfloat162float(hx));
    __nv_bfloat16 ly = __float2bfloat16(y - __bfloat162float(hy));
    hi = ((u32)__bfloat16_as_ushort(hy) << 16) | (u32)__bfloat16_as_ushort(hx);
    lo = ((u32)__bfloat16_as_ushort(ly) << 16) | (u32)__bfloat16_as_ushort(lx);
}

// m16n8k16 bf16 MMA, fp32 accumulate in place.  Non-arch-suffixed: works on plain sm_103.
__device__ __forceinline__ void mma16816(float* d, const u32* a, const u32* b) {
    asm volatile(
        "mma.sync.aligned.m16n8k16.row.col.f32.bf16.bf16.f32 "
        "{%0,%1,%2,%3}, {%4,%5,%6,%7}, {%8,%9}, {%0,%1,%2,%3};"
        : "+f"(d[0]), "+f"(d[1]), "+f"(d[2]), "+f"(d[3])
        : "r"(a[0]), "r"(a[1]), "r"(a[2]), "r"(a[3]), "r"(b[0]), "r"(b[1]));
}

// ======================= device scratch =======================
__device__ u32    g_Qh[BATCH * SEQ * DDIM / 2];  // bf16x2 [b][s][d], Q pre-scaled 1/8
__device__ u32    g_Ql[BATCH * SEQ * DDIM / 2];
__device__ u32    g_Kh[BATCH * SEQ * DDIM / 2];
__device__ u32    g_Kl[BATCH * SEQ * DDIM / 2];
__device__ __half g_Eh[(size_t)BATCH * SEQ * SEQ];  // exp(score-8), fp16, 128 MB
__device__ float  g_PE[SEQ * HDIM];
__device__ float  g_w[BATCH * SEQ];
__device__ float  g_Z[BATCH * SEQ];
__device__ float  g_c[BATCH * SEQ];
__device__ float  g_wvf[HDIM];

// ======================= PE table =======================
__global__ void k_pe() {
    int idx = blockIdx.x * 256 + threadIdx.x;
    if (idx >= SEQ * HDIM) return;
    int s = idx / HDIM, h = idx % HDIM;
    double denom = pow(10000.0, (double)(h & ~1) / 128.0);
    float ang = (float)((double)s / denom);
    g_PE[idx] = (h & 1) ? cosf(ang) : sinf(ang);
}

__global__ void k_wvf(const float* __restrict__ Wv, const float* __restrict__ Wf) {
    int h = threadIdx.x;
    float acc = 0.f;
#pragma unroll 16
    for (int d = 0; d < DDIM; d++) acc += Wv[h * DDIM + d] * Wf[d];
    g_wvf[h] = acc;
}

__global__ void k_rowdot(const float* __restrict__ x) {
    int row  = blockIdx.x * 8 + (threadIdx.x >> 5);
    int lane = threadIdx.x & 31;
    int s = row & (SEQ - 1);
    const float4* xr = (const float4*)(x + (size_t)row * HDIM);
    const float4* pe = (const float4*)(g_PE + (size_t)s * HDIM);
    const float4* wv = (const float4*)g_wvf;
    float4 xv = xr[lane], pv = pe[lane], wf = wv[lane];
    float acc = (xv.x + pv.x) * wf.x + (xv.y + pv.y) * wf.y +
                (xv.z + pv.z) * wf.z + (xv.w + pv.w) * wf.w;
#pragma unroll
    for (int off = 16; off; off >>= 1) acc += __shfl_xor_sync(0xFFFFFFFFu, acc, off);
    if (lane == 0) g_w[row] = acc;
}

// ======================= projection -> bf16 hi/lo =======================
__global__ void __launch_bounds__(256) k_proj(const float* __restrict__ x,
                                              const float* __restrict__ Wq,
                                              const float* __restrict__ Wk) {
    extern __shared__ float sm[];
    float* As = sm;                 // [64][128]  xp row-major
    float* Ws = sm + 64 * 128;      // [128][128] cols 0-63 Wq, 64-127 Wk
    int b = blockIdx.y, s0 = blockIdx.x * 64;
    int tid = threadIdx.x;

    const float4* wq4 = (const float4*)Wq;
    const float4* wk4 = (const float4*)Wk;
    for (int i = tid; i < 2048; i += 256) {
        int h = i >> 4, c4 = i & 15;
        ((float4*)(Ws + h * 128))[c4]      = wq4[i];
        ((float4*)(Ws + h * 128 + 64))[c4] = wk4[i];
    }
    for (int i = tid; i < 2048; i += 256) {
        int sl = i >> 5, c4 = i & 31;
        float4 xv = ((const float4*)(x + (size_t)(b * SEQ + s0 + sl) * HDIM))[c4];
        float4 pv = ((const float4*)(g_PE + (size_t)(s0 + sl) * HDIM))[c4];
        xv.x += pv.x; xv.y += pv.y; xv.z += pv.z; xv.w += pv.w;
        ((float4*)(As + sl * 128))[c4] = xv;
    }
    __syncthreads();

    int tx = tid & 15, ty = tid >> 4;
    u64 acc2[4][4];
#pragma unroll
    for (int i = 0; i < 4; i++)
#pragma unroll
        for (int j = 0; j < 4; j++) acc2[i][j] = 0ull;

#pragma unroll 4
    for (int h = 0; h < 128; h++) {
        ulonglong2 bq = *(const ulonglong2*)(Ws + h * 128 + tx * 4);
        ulonglong2 bk = *(const ulonglong2*)(Ws + h * 128 + 64 + tx * 4);
        u64 b2[4] = {bq.x, bq.y, bk.x, bk.y};
#pragma unroll
        for (int i = 0; i < 4; i++) {
            u64 ad = dup2(As[(ty * 4 + i) * 128 + h]);
#pragma unroll
            for (int j = 0; j < 4; j++) acc2[i][j] = ffma2(ad, b2[j], acc2[i][j]);
        }
    }

#pragma unroll
    for (int i = 0; i < 4; i++) {
        int q = s0 + ty * 4 + i;
        size_t ro = (size_t)(b * SEQ + q) * 32;
#pragma unroll
        for (int j2 = 0; j2 < 2; j2++) {
            float2 fq = unpack2(acc2[i][j2]);
            float2 fk = unpack2(acc2[i][j2 + 2]);
            u32 hi, lo;
            split2(fq.x * 0.125f, fq.y * 0.125f, hi, lo);
            g_Qh[ro + tx * 2 + j2] = hi;
            g_Ql[ro + tx * 2 + j2] = lo;
            split2(fk.x, fk.y, hi, lo);
            g_Kh[ro + tx * 2 + j2] = hi;
            g_Kl[ro + tx * 2 + j2] = lo;
        }
    }
}

// ======================= HMMA scores: E = exp(QK^T - 8) fp16, Z = col sums =======================
// Block: 128 k-cols (blockIdx.x) x all 2048 q for one batch. 8 warps, warp owns 16 k-cols.
// K fragments resident in registers; Q tiles staged in swizzled smem.
// smem (u32 units): Qh_s[4096] | Ql_s[4096] | Stg[8192]  = 64 KB
__global__ void __launch_bounds__(256, 2) k_scores(void) {
    extern __shared__ u32 smu[];
    u32* Qh_s = smu;
    u32* Ql_s = smu + 4096;
    u32* Stg  = smu + 8192;

    int tid = threadIdx.x, lane = tid & 31, w = tid >> 5;
    int b = blockIdx.y, k0 = blockIdx.x * 128;

    // --- load resident B (K) fragments: warp's 16 k-cols, 4 k-steps, hi+lo ---
    u32 Bh[2][4][2], Bl[2][4][2];
#pragma unroll
    for (int nt = 0; nt < 2; nt++) {
        int rowg = b * SEQ + k0 + w * 16 + nt * 8 + (lane >> 2);
        int base = rowg * 32;
#pragma unroll
        for (int ks = 0; ks < 4; ks++) {
            Bh[nt][ks][0] = g_Kh[base + 8 * ks + (lane & 3)];
            Bh[nt][ks][1] = g_Kh[base + 8 * ks + 4 + (lane & 3)];
            Bl[nt][ks][0] = g_Kl[base + 8 * ks + (lane & 3)];
            Bl[nt][ks][1] = g_Kl[base + 8 * ks + 4 + (lane & 3)];
        }
    }

    float2 csum[2];
    csum[0] = make_float2(0.f, 0.f);
    csum[1] = make_float2(0.f, 0.f);

    for (int qi = 0; qi < 16; qi++) {
        int q0 = qi * 128;
        __syncthreads();  // Qs + Stg from previous iteration fully consumed

        // fill swizzled Q tiles (uint4 granularity; swizzle on 16B groups)
        const uint4* srcH = (const uint4*)g_Qh + (size_t)(b * SEQ + q0) * 8;
        const uint4* srcL = (const uint4*)g_Ql + (size_t)(b * SEQ + q0) * 8;
        uint4* dH = (uint4*)Qh_s;
        uint4* dL = (uint4*)Ql_s;
        for (int i = tid; i < 1024; i += 256) {
            int row = i >> 3, u4 = i & 7;
            int d = row * 8 + (u4 ^ (row & 7));
            dH[d] = srcH[i];
            dL[d] = srcL[i];
        }
        __syncthreads();

        float D[8][2][4];
#pragma unroll
        for (int m = 0; m < 8; m++)
#pragma unroll
            for (int nt = 0; nt < 2; nt++)
#pragma unroll
                for (int j = 0; j < 4; j++) D[m][nt][j] = 0.f;

#pragma unroll
        for (int ks = 0; ks < 4; ks++) {
#pragma unroll
            for (int m = 0; m < 8; m++) {
                int r0 = m * 16 + (lane >> 2);
                int sw = (r0 & 7) << 2;
                int wlo = 8 * ks + (lane & 3), whi = wlo + 4;
                u32 Ah[4], Al[4];
                Ah[0] = Qh_s[r0 * 32 + (wlo ^ sw)];
                Ah[1] = Qh_s[(r0 + 8) * 32 + (wlo ^ sw)];
                Ah[2] = Qh_s[r0 * 32 + (whi ^ sw)];
                Ah[3] = Qh_s[(r0 + 8) * 32 + (whi ^ sw)];
                Al[0] = Ql_s[r0 * 32 + (wlo ^ sw)];
                Al[1] = Ql_s[(r0 + 8) * 32 + (wlo ^ sw)];
                Al[2] = Ql_s[r0 * 32 + (whi ^ sw)];
                Al[3] = Ql_s[(r0 + 8) * 32 + (whi ^ sw)];
#pragma unroll
                for (int nt = 0; nt < 2; nt++) {
                    mma16816(D[m][nt], Ah, Bh[nt][ks]);
                    mma16816(D[m][nt], Ah, Bl[nt][ks]);
                    mma16816(D[m][nt], Al, Bh[nt][ks]);
                }
            }
        }

        // epilogue: exp(s-8) -> fp16, stage (swizzled), accumulate Z from rounded values
#pragma unroll
        for (int m = 0; m < 8; m++) {
            int rloc = m * 16 + (lane >> 2);
            int sw = (rloc & 7) << 2;
#pragma unroll
            for (int nt = 0; nt < 2; nt++) {
                int wd = w * 8 + nt * 4 + (lane & 3);
                __half2 h2 = __floats2half2_rn(__expf(D[m][nt][0] - 8.f),
                                               __expf(D[m][nt][1] - 8.f));
                *(__half2*)&Stg[rloc * 64 + (wd ^ sw)] = h2;
                float2 f = __half22float2(h2);
                csum[nt].x += f.x; csum[nt].y += f.y;

                h2 = __floats2half2_rn(__expf(D[m][nt][2] - 8.f),
                                       __expf(D[m][nt][3] - 8.f));
                *(__half2*)&Stg[(rloc + 8) * 64 + (wd ^ sw)] = h2;
                f = __half22float2(h2);
                csum[nt].x += f.x; csum[nt].y += f.y;
            }
        }
        __syncthreads();

        // coalesced store of the 128x128 fp16 tile (256B per row)
        const uint4* St4 = (const uint4*)Stg;
#pragma unroll
        for (int it = 0; it < 8; it++) {
            int row = it * 16 + (tid >> 4);
            int u = tid & 15;
            uint4 v = St4[row * 16 + (u ^ (row & 7))];
            *(uint4*)(g_Eh + (size_t)(b * SEQ + q0 + row) * SEQ + k0 + u * 8) = v;
        }
    }

    // Z: reduce column sums over row-groups (lanes differing in bits 2..4)
#pragma unroll
    for (int off = 4; off <= 16; off <<= 1) {
#pragma unroll
        for (int nt = 0; nt < 2; nt++) {
            csum[nt].x += __shfl_xor_sync(0xFFFFFFFFu, csum[nt].x, off);
            csum[nt].y += __shfl_xor_sync(0xFFFFFFFFu, csum[nt].y, off);
        }
    }
    if (lane < 4) {
#pragma unroll
        for (int nt = 0; nt < 2; nt++) {
            int idx = b * SEQ + k0 + w * 16 + nt * 8 + lane * 2;
            g_Z[idx]     = csum[nt].x;
            g_Z[idx + 1] = csum[nt].y;
        }
    }
}

// ======================= c = w / Z =======================
__global__ void k_div() {
    int i = blockIdx.x * 256 + threadIdx.x;
    g_c[i] = g_w[i] / g_Z[i];
}

// ======================= out[b,q] = bf + E[b,q,:] . c[b,:] =======================
__global__ void __launch_bounds__(256) k_out(const float* __restrict__ bf,
                                             float* __restrict__ out) {
    __shared__ float cs[SEQ];
    int b = blockIdx.y, q0 = blockIdx.x * 8;
    int tid = threadIdx.x;
    for (int i = tid; i < SEQ; i += 256) cs[i] = g_c[b * SEQ + i];
    __syncthreads();
    int w = tid >> 5, lane = tid & 31;
    int q = q0 + w;
    const uint4* E4 = (const uint4*)(g_Eh + (size_t)(b * SEQ + q) * SEQ);
    float acc = 0.f;
#pragma unroll 2
    for (int i = lane; i < 256; i += 32) {   // 256 uint4 (8 halves each) per row
        uint4 v = E4[i];
        int base = i * 8;
        float4 c0 = *(const float4*)&cs[base];
        float4 c1 = *(const float4*)&cs[base + 4];
        float2 f;
        f = __half22float2(*(__half2*)&v.x); acc += f.x * c0.x + f.y * c0.y;
        f = __half22float2(*(__half2*)&v.y); acc += f.x * c0.z + f.y * c0.w;
        f = __half22float2(*(__half2*)&v.z); acc += f.x * c1.x + f.y * c1.y;
        f = __half22float2(*(__half2*)&v.w); acc += f.x * c1.z + f.y * c1.w;
    }
#pragma unroll
    for (int off = 16; off; off >>= 1) acc += __shfl_xor_sync(0xFFFFFFFFu, acc, off);
    if (lane == 0) out[b * SEQ + q] = acc + bf[0];
}

// ======================= launch =======================
extern "C" void kernel_launch(void* const* d_in, const int* in_sizes, int n_in,
                              void* d_out, int out_size) {
    const float* x  = (const float*)d_in[0];
    const float* Wq = (const float*)d_in[1];
    const float* Wk = (const float*)d_in[2];
    const float* Wv = (const float*)d_in[3];
    const float* Wf = (const float*)d_in[4];
    const float* bf = (const float*)d_in[5];
    float* out = (float*)d_out;

    cudaFuncSetAttribute(k_proj,   cudaFuncAttributeMaxDynamicSharedMemorySize, 98304);
    cudaFuncSetAttribute(k_scores, cudaFuncAttributeMaxDynamicSharedMemorySize, 65536);

    k_pe<<<(SEQ * HDIM + 255) / 256, 256>>>();
    k_wvf<<<1, 128>>>(Wv, Wf);
    k_rowdot<<<(BATCH * SEQ) / 8, 256>>>(x);
    k_proj<<<dim3(SEQ / 64, BATCH), 256, 98304>>>(x, Wq, Wk);
    k_scores<<<dim3(16, BATCH), 256, 65536>>>();
    k_div<<<(BATCH * SEQ) / 256, 256>>>();
    k_out<<<dim3(SEQ / 8, BATCH), 256>>>(bf, out);
}

// round 13
// speedup vs baseline: 1.6987x; 1.0635x over previous
#include <cuda_runtime.h>
#include <cuda_bf16.h>
#include <cuda_fp16.h>
#include <math.h>
#include <stdint.h>

#define BATCH 16
#define SEQ   2048
#define HDIM  128
#define DDIM  64

typedef unsigned long long u64;
typedef unsigned int u32;

// ======================= small helpers =======================
__device__ __forceinline__ u64 ffma2(u64 a, u64 b, u64 c) {
    u64 d;
    asm("fma.rn.f32x2 %0, %1, %2, %3;" : "=l"(d) : "l"(a), "l"(b), "l"(c));
    return d;
}
__device__ __forceinline__ u64 dup2(float x) {
    u64 d;
    asm("mov.b64 %0, {%1, %1};" : "=l"(d) : "f"(x));
    return d;
}
__device__ __forceinline__ float2 unpack2(u64 v) {
    float2 f;
    asm("mov.b64 {%0, %1}, %2;" : "=f"(f.x), "=f"(f.y) : "l"(v));
    return f;
}
// split (x,y) into packed bf16x2 hi and lo words (low half = x)
__device__ __forceinline__ void split2(float x, float y, u32& hi, u32& lo) {
    __nv_bfloat16 hx = __float2bfloat16(x);
    __nv_bfloat16 hy = __float2bfloat16(y);
    __nv_bfloat16 lx = __float2bfloat16(x - __bfloat162float(hx));
    __nv_bfloat16 ly = __float2bfloat16(y - __bfloat162float(hy));
    hi = ((u32)__bfloat16_as_ushort(hy) << 16) | (u32)__bfloat16_as_ushort(hx);
    lo = ((u32)__bfloat16_as_ushort(ly) << 16) | (u32)__bfloat16_as_ushort(lx);
}

// m16n8k16 bf16 MMA, fp32 accumulate in place (non-arch-suffixed, works on sm_103)
__device__ __forceinline__ void mma16816(float* d, const u32* a, const u32* b) {
    asm volatile(
        "mma.sync.aligned.m16n8k16.row.col.f32.bf16.bf16.f32 "
        "{%0,%1,%2,%3}, {%4,%5,%6,%7}, {%8,%9}, {%0,%1,%2,%3};"
        : "+f"(d[0]), "+f"(d[1]), "+f"(d[2]), "+f"(d[3])
        : "r"(a[0]), "r"(a[1]), "r"(a[2]), "r"(a[3]), "r"(b[0]), "r"(b[1]));
}
// ldmatrix x4 (sm_75+, non-suffixed)
__device__ __forceinline__ void ldm4(u32* r, u32 addr) {
    asm volatile("ldmatrix.sync.aligned.m8n8.x4.shared.b16 {%0,%1,%2,%3}, [%4];"
                 : "=r"(r[0]), "=r"(r[1]), "=r"(r[2]), "=r"(r[3]) : "r"(addr));
}
// cp.async 16B (sm_80+, non-suffixed)
__device__ __forceinline__ void cpa16(u32 dst, const void* src) {
    asm volatile("cp.async.cg.shared.global [%0], [%1], 16;" :: "r"(dst), "l"(src));
}
#define CP_COMMIT() asm volatile("cp.async.commit_group;" ::: "memory")
#define CP_WAIT(n)  asm volatile("cp.async.wait_group %0;" :: "n"(n) : "memory")

__device__ __forceinline__ u32 smem_u32(const void* p) {
    u32 a;
    asm("{ .reg .u64 t; cvta.to.shared.u64 t, %1; cvt.u32.u64 %0, t; }" : "=r"(a) : "l"(p));
    return a;
}

// ======================= device scratch =======================
__device__ u32    g_Qh[BATCH * SEQ * DDIM / 2];  // bf16x2 [b][s][d], Q pre-scaled 1/8
__device__ u32    g_Ql[BATCH * SEQ * DDIM / 2];
__device__ u32    g_Kh[BATCH * SEQ * DDIM / 2];
__device__ u32    g_Kl[BATCH * SEQ * DDIM / 2];
__device__ __half g_Eh[(size_t)BATCH * SEQ * SEQ];  // exp(score-8), fp16, 128 MB
__device__ float  g_PE[SEQ * HDIM];
__device__ float  g_w[BATCH * SEQ];
__device__ float  g_Z[BATCH * SEQ];
__device__ float  g_c[BATCH * SEQ];
__device__ float  g_wvf[HDIM];

// ======================= PE table =======================
__global__ void k_pe() {
    int idx = blockIdx.x * 256 + threadIdx.x;
    if (idx >= SEQ * HDIM) return;
    int s = idx / HDIM, h = idx % HDIM;
    double denom = pow(10000.0, (double)(h & ~1) / 128.0);
    float ang = (float)((double)s / denom);
    g_PE[idx] = (h & 1) ? cosf(ang) : sinf(ang);
}

__global__ void k_wvf(const float* __restrict__ Wv, const float* __restrict__ Wf) {
    int h = threadIdx.x;
    float acc = 0.f;
#pragma unroll 16
    for (int d = 0; d < DDIM; d++) acc += Wv[h * DDIM + d] * Wf[d];
    g_wvf[h] = acc;
}

__global__ void k_rowdot(const float* __restrict__ x) {
    int row  = blockIdx.x * 8 + (threadIdx.x >> 5);
    int lane = threadIdx.x & 31;
    int s = row & (SEQ - 1);
    const float4* xr = (const float4*)(x + (size_t)row * HDIM);
    const float4* pe = (const float4*)(g_PE + (size_t)s * HDIM);
    const float4* wv = (const float4*)g_wvf;
    float4 xv = xr[lane], pv = pe[lane], wf = wv[lane];
    float acc = (xv.x + pv.x) * wf.x + (xv.y + pv.y) * wf.y +
                (xv.z + pv.z) * wf.z + (xv.w + pv.w) * wf.w;
#pragma unroll
    for (int off = 16; off; off >>= 1) acc += __shfl_xor_sync(0xFFFFFFFFu, acc, off);
    if (lane == 0) g_w[row] = acc;
}

// ======================= projection -> bf16 hi/lo =======================
__global__ void __launch_bounds__(256) k_proj(const float* __restrict__ x,
                                              const float* __restrict__ Wq,
                                              const float* __restrict__ Wk) {
    extern __shared__ float sm[];
    float* As = sm;                 // [64][128]  xp row-major
    float* Ws = sm + 64 * 128;      // [128][128] cols 0-63 Wq, 64-127 Wk
    int b = blockIdx.y, s0 = blockIdx.x * 64;
    int tid = threadIdx.x;

    const float4* wq4 = (const float4*)Wq;
    const float4* wk4 = (const float4*)Wk;
    for (int i = tid; i < 2048; i += 256) {
        int h = i >> 4, c4 = i & 15;
        ((float4*)(Ws + h * 128))[c4]      = wq4[i];
        ((float4*)(Ws + h * 128 + 64))[c4] = wk4[i];
    }
    for (int i = tid; i < 2048; i += 256) {
        int sl = i >> 5, c4 = i & 31;
        float4 xv = ((const float4*)(x + (size_t)(b * SEQ + s0 + sl) * HDIM))[c4];
        float4 pv = ((const float4*)(g_PE + (size_t)(s0 + sl) * HDIM))[c4];
        xv.x += pv.x; xv.y += pv.y; xv.z += pv.z; xv.w += pv.w;
        ((float4*)(As + sl * 128))[c4] = xv;
    }
    __syncthreads();

    int tx = tid & 15, ty = tid >> 4;
    u64 acc2[4][4];
#pragma unroll
    for (int i = 0; i < 4; i++)
#pragma unroll
        for (int j = 0; j < 4; j++) acc2[i][j] = 0ull;

#pragma unroll 4
    for (int h = 0; h < 128; h++) {
        ulonglong2 bq = *(const ulonglong2*)(Ws + h * 128 + tx * 4);
        ulonglong2 bk = *(const ulonglong2*)(Ws + h * 128 + 64 + tx * 4);
        u64 b2[4] = {bq.x, bq.y, bk.x, bk.y};
#pragma unroll
        for (int i = 0; i < 4; i++) {
            u64 ad = dup2(As[(ty * 4 + i) * 128 + h]);
#pragma unroll
            for (int j = 0; j < 4; j++) acc2[i][j] = ffma2(ad, b2[j], acc2[i][j]);
        }
    }

#pragma unroll
    for (int i = 0; i < 4; i++) {
        int q = s0 + ty * 4 + i;
        size_t ro = (size_t)(b * SEQ + q) * 32;
#pragma unroll
        for (int j2 = 0; j2 < 2; j2++) {
            float2 fq = unpack2(acc2[i][j2]);
            float2 fk = unpack2(acc2[i][j2 + 2]);
            u32 hi, lo;
            split2(fq.x * 0.125f, fq.y * 0.125f, hi, lo);
            g_Qh[ro + tx * 2 + j2] = hi;
            g_Ql[ro + tx * 2 + j2] = lo;
            split2(fk.x, fk.y, hi, lo);
            g_Kh[ro + tx * 2 + j2] = hi;
            g_Kl[ro + tx * 2 + j2] = lo;
        }
    }
}

// ======================= HMMA scores (ldmatrix + cp.async double-buffer) =======================
// smem: QBuf0 (Qh 16K | Ql 16K) | QBuf1 (32K) | Stg (32K)  = 96 KB
#define QBUF   32768
#define QL_OFF 16384
#define STG_U32 16384   // Stg starts at u32 index 16384 (byte 65536)

__device__ __forceinline__ void fill_async(u32 dst, int b, int q0, int tid) {
    const uint4* sH = (const uint4*)g_Qh + (size_t)(b * SEQ + q0) * 8;
    const uint4* sL = (const uint4*)g_Ql + (size_t)(b * SEQ + q0) * 8;
#pragma unroll
    for (int it = 0; it < 4; it++) {
        int i = it * 256 + tid;
        int row = i >> 3, u = i & 7;
        u32 d = (u32)(((row << 3) + (u ^ (row & 7))) << 4);
        cpa16(dst + d, sH + i);
        cpa16(dst + QL_OFF + d, sL + i);
    }
}

__global__ void __launch_bounds__(256, 2) k_scores(void) {
    extern __shared__ u32 smu[];
    u32 smb = smem_u32(smu);
    u32* Stg = smu + STG_U32;

    int tid = threadIdx.x, lane = tid & 31, w = tid >> 5;
    int b = blockIdx.y, k0 = blockIdx.x * 128;

    // resident B (K) fragments: warp's 16 k-cols, 4 k-steps, hi+lo
    u32 Bh[2][4][2], Bl[2][4][2];
#pragma unroll
    for (int nt = 0; nt < 2; nt++) {
        int rowg = b * SEQ + k0 + w * 16 + nt * 8 + (lane >> 2);
        int base = rowg * 32;
#pragma unroll
        for (int ks = 0; ks < 4; ks++) {
            Bh[nt][ks][0] = g_Kh[base + 8 * ks + (lane & 3)];
            Bh[nt][ks][1] = g_Kh[base + 8 * ks + 4 + (lane & 3)];
            Bl[nt][ks][0] = g_Kl[base + 8 * ks + (lane & 3)];
            Bl[nt][ks][1] = g_Kl[base + 8 * ks + 4 + (lane & 3)];
        }
    }

    // prefetch q-tile 0
    fill_async(smb, b, 0, tid);
    CP_COMMIT();

    float2 csum[2];
    csum[0] = make_float2(0.f, 0.f);
    csum[1] = make_float2(0.f, 0.f);

    // per-lane ldmatrix address pieces: row = m*16 + (lane&15), colunit = ks*2 + (lane>>4)
    u32 rbase = (u32)((lane & 15) * 128);
    u32 rx    = (u32)(lane & 7);
    u32 cadd  = (u32)(lane >> 4);

    for (int qi = 0; qi < 16; qi++) {
        int q0 = qi * 128;
        if (qi < 15) {
            fill_async(smb + (u32)(((qi + 1) & 1) * QBUF), b, q0 + 128, tid);
            CP_COMMIT();
            CP_WAIT(1);
        } else {
            CP_WAIT(0);
        }
        __syncthreads();   // current buffer visible to all; prev Stg fully drained

        u32 qb = smb + (u32)((qi & 1) * QBUF);

        float D[8][2][4];
#pragma unroll
        for (int m = 0; m < 8; m++)
#pragma unroll
            for (int nt = 0; nt < 2; nt++)
#pragma unroll
                for (int j = 0; j < 4; j++) D[m][nt][j] = 0.f;

#pragma unroll
        for (int m = 0; m < 8; m++) {
            u32 abase = qb + (u32)(m * 2048) + rbase;
#pragma unroll
            for (int ks = 0; ks < 4; ks++) {
                u32 a = abase + ((((u32)(ks * 2) + cadd) ^ rx) << 4);
                u32 Ah[4], Al[4];
                ldm4(Ah, a);
                ldm4(Al, a + QL_OFF);
#pragma unroll
                for (int nt = 0; nt < 2; nt++) {
                    mma16816(D[m][nt], Ah, Bh[nt][ks]);
                    mma16816(D[m][nt], Ah, Bl[nt][ks]);
                    mma16816(D[m][nt], Al, Bh[nt][ks]);
                }
            }
        }

        // epilogue: exp(s-8) -> fp16, stage swizzled, accumulate Z from rounded values
#pragma unroll
        for (int m = 0; m < 8; m++) {
            int rloc = m * 16 + (lane >> 2);
            int sw = (rloc & 7) << 2;
#pragma unroll
            for (int nt = 0; nt < 2; nt++) {
                int wd = w * 8 + nt * 4 + (lane & 3);
                __half2 h2 = __floats2half2_rn(__expf(D[m][nt][0] - 8.f),
                                               __expf(D[m][nt][1] - 8.f));
                *(__half2*)&Stg[rloc * 64 + (wd ^ sw)] = h2;
                float2 f = __half22float2(h2);
                csum[nt].x += f.x; csum[nt].y += f.y;

                h2 = __floats2half2_rn(__expf(D[m][nt][2] - 8.f),
                                       __expf(D[m][nt][3] - 8.f));
                *(__half2*)&Stg[(rloc + 8) * 64 + (wd ^ sw)] = h2;
                f = __half22float2(h2);
                csum[nt].x += f.x; csum[nt].y += f.y;
            }
        }
        __syncthreads();

        // coalesced store of the 128x128 fp16 tile
        const uint4* St4 = (const uint4*)Stg;
#pragma unroll
        for (int it = 0; it < 8; it++) {
            int row = it * 16 + (tid >> 4);
            int u = tid & 15;
            uint4 v = St4[row * 16 + (u ^ (row & 7))];
            *(uint4*)(g_Eh + (size_t)(b * SEQ + q0 + row) * SEQ + k0 + u * 8) = v;
        }
    }

    // Z: reduce column sums across row-groups
#pragma unroll
    for (int off = 4; off <= 16; off <<= 1) {
#pragma unroll
        for (int nt = 0; nt < 2; nt++) {
            csum[nt].x += __shfl_xor_sync(0xFFFFFFFFu, csum[nt].x, off);
            csum[nt].y += __shfl_xor_sync(0xFFFFFFFFu, csum[nt].y, off);
        }
    }
    if (lane < 4) {
#pragma unroll
        for (int nt = 0; nt < 2; nt++) {
            int idx = b * SEQ + k0 + w * 16 + nt * 8 + lane * 2;
            g_Z[idx]     = csum[nt].x;
            g_Z[idx + 1] = csum[nt].y;
        }
    }
}

// ======================= c = w / Z =======================
__global__ void k_div() {
    int i = blockIdx.x * 256 + threadIdx.x;
    g_c[i] = g_w[i] / g_Z[i];
}

// ======================= out[b,q] = bf + E[b,q,:] . c[b,:] =======================
__global__ void __launch_bounds__(256) k_out(const float* __restrict__ bf,
                                             float* __restrict__ out) {
    __shared__ float cs[SEQ];
    int b = blockIdx.y, q0 = blockIdx.x * 8;
    int tid = threadIdx.x;
    for (int i = tid; i < SEQ; i += 256) cs[i] = g_c[b * SEQ + i];
    __syncthreads();
    int w = tid >> 5, lane = tid & 31;
    int q = q0 + w;
    const uint4* E4 = (const uint4*)(g_Eh + (size_t)(b * SEQ + q) * SEQ);
    float acc = 0.f;
#pragma unroll 2
    for (int i = lane; i < 256; i += 32) {
        uint4 v = E4[i];
        int base = i * 8;
        float4 c0 = *(const float4*)&cs[base];
        float4 c1 = *(const float4*)&cs[base + 4];
        float2 f;
        f = __half22float2(*(__half2*)&v.x); acc += f.x * c0.x + f.y * c0.y;
        f = __half22float2(*(__half2*)&v.y); acc += f.x * c0.z + f.y * c0.w;
        f = __half22float2(*(__half2*)&v.z); acc += f.x * c1.x + f.y * c1.y;
        f = __half22float2(*(__half2*)&v.w); acc += f.x * c1.z + f.y * c1.w;
    }
#pragma unroll
    for (int off = 16; off; off >>= 1) acc += __shfl_xor_sync(0xFFFFFFFFu, acc, off);
    if (lane == 0) out[b * SEQ + q] = acc + bf[0];
}

// ======================= launch =======================
extern "C" void kernel_launch(void* const* d_in, const int* in_sizes, int n_in,
                              void* d_out, int out_size) {
    const float* x  = (const float*)d_in[0];
    const float* Wq = (const float*)d_in[1];
    const float* Wk = (const float*)d_in[2];
    const float* Wv = (const float*)d_in[3];
    const float* Wf = (const float*)d_in[4];
    const float* bf = (const float*)d_in[5];
    float* out = (float*)d_out;

    cudaFuncSetAttribute(k_proj,   cudaFuncAttributeMaxDynamicSharedMemorySize, 98304);
    cudaFuncSetAttribute(k_scores, cudaFuncAttributeMaxDynamicSharedMemorySize, 98304);

    k_pe<<<(SEQ * HDIM + 255) / 256, 256>>>();
    k_wvf<<<1, 128>>>(Wv, Wf);
    k_rowdot<<<(BATCH * SEQ) / 8, 256>>>(x);
    k_proj<<<dim3(SEQ / 64, BATCH), 256, 98304>>>(x, Wq, Wk);
    k_scores<<<dim3(16, BATCH), 256, 98304>>>();
    k_div<<<(BATCH * SEQ) / 256, 256>>>();
    k_out<<<dim3(SEQ / 8, BATCH), 256>>>(bf, out);
}

// round 14
// speedup vs baseline: 1.7624x; 1.0375x over previous
#include <cuda_runtime.h>
#include <cuda_bf16.h>
#include <cuda_fp16.h>
#include <math.h>
#include <stdint.h>

#define BATCH 16
#define SEQ   2048
#define HDIM  128
#define DDIM  64

typedef unsigned long long u64;
typedef unsigned int u32;

// ======================= small helpers =======================
// split (x,y) into packed bf16x2 hi and lo words (low half = x)
__device__ __forceinline__ void split2(float x, float y, u32& hi, u32& lo) {
    __nv_bfloat16 hx = __float2bfloat16(x);
    __nv_bfloat16 hy = __float2bfloat16(y);
    __nv_bfloat16 lx = __float2bfloat16(x - __bfloat162float(hx));
    __nv_bfloat16 ly = __float2bfloat16(y - __bfloat162float(hy));
    hi = ((u32)__bfloat16_as_ushort(hy) << 16) | (u32)__bfloat16_as_ushort(hx);
    lo = ((u32)__bfloat16_as_ushort(ly) << 16) | (u32)__bfloat16_as_ushort(lx);
}

// m16n8k16 bf16 MMA, fp32 accumulate in place (non-arch-suffixed, works on sm_103)
__device__ __forceinline__ void mma16816(float* d, const u32* a, const u32* b) {
    asm volatile(
        "mma.sync.aligned.m16n8k16.row.col.f32.bf16.bf16.f32 "
        "{%0,%1,%2,%3}, {%4,%5,%6,%7}, {%8,%9}, {%0,%1,%2,%3};"
        : "+f"(d[0]), "+f"(d[1]), "+f"(d[2]), "+f"(d[3])
        : "r"(a[0]), "r"(a[1]), "r"(a[2]), "r"(a[3]), "r"(b[0]), "r"(b[1]));
}
// ldmatrix x4 (sm_75+, non-suffixed)
__device__ __forceinline__ void ldm4(u32* r, u32 addr) {
    asm volatile("ldmatrix.sync.aligned.m8n8.x4.shared.b16 {%0,%1,%2,%3}, [%4];"
                 : "=r"(r[0]), "=r"(r[1]), "=r"(r[2]), "=r"(r[3]) : "r"(addr));
}
// cp.async 16B (sm_80+, non-suffixed)
__device__ __forceinline__ void cpa16(u32 dst, const void* src) {
    asm volatile("cp.async.cg.shared.global [%0], [%1], 16;" :: "r"(dst), "l"(src));
}
#define CP_COMMIT() asm volatile("cp.async.commit_group;" ::: "memory")
#define CP_WAIT(n)  asm volatile("cp.async.wait_group %0;" :: "n"(n) : "memory")

__device__ __forceinline__ u32 smem_u32(const void* p) {
    u32 a;
    asm("{ .reg .u64 t; cvta.to.shared.u64 t, %1; cvt.u32.u64 %0, t; }" : "=r"(a) : "l"(p));
    return a;
}

// ======================= device scratch =======================
__device__ u32    g_Qh[BATCH * SEQ * DDIM / 2];  // bf16x2 [b][s][d-pair], Q pre-scaled 1/8
__device__ u32    g_Ql[BATCH * SEQ * DDIM / 2];
__device__ u32    g_Kh[BATCH * SEQ * DDIM / 2];
__device__ u32    g_Kl[BATCH * SEQ * DDIM / 2];
__device__ __half g_Eh[(size_t)BATCH * SEQ * SEQ];  // exp(score-8), fp16, 128 MB
__device__ float  g_PE[SEQ * HDIM];
__device__ float  g_w[BATCH * SEQ];
__device__ float  g_Z[BATCH * SEQ];
__device__ float  g_wvf[HDIM];
__device__ u32    g_WTh[128 * 64];   // transposed+split weights: [n][h-pair] bf16x2 hi
__device__ u32    g_WTl[128 * 64];   // n<64: Wq col n; n>=64: Wk col n-64

// ======================= PE table =======================
__global__ void k_pe() {
    int idx = blockIdx.x * 256 + threadIdx.x;
    if (idx >= SEQ * HDIM) return;
    int s = idx / HDIM, h = idx % HDIM;
    double denom = pow(10000.0, (double)(h & ~1) / 128.0);
    float ang = (float)((double)s / denom);
    g_PE[idx] = (h & 1) ? cosf(ang) : sinf(ang);
}

__global__ void k_wvf(const float* __restrict__ Wv, const float* __restrict__ Wf) {
    int h = threadIdx.x;
    float acc = 0.f;
#pragma unroll 16
    for (int d = 0; d < DDIM; d++) acc += Wv[h * DDIM + d] * Wf[d];
    g_wvf[h] = acc;
}

// transpose + bf16-split the weights into B-fragment-friendly layout
__global__ void k_wsplit(const float* __restrict__ Wq, const float* __restrict__ Wk) {
    int idx = blockIdx.x * 256 + threadIdx.x;   // 128 n * 64 h-pairs
    if (idx >= 128 * 64) return;
    int n = idx >> 6, hp = idx & 63;
    const float* W = (n < 64) ? Wq : Wk;
    int d = n & 63;
    float w0 = W[(hp * 2) * DDIM + d];
    float w1 = W[(hp * 2 + 1) * DDIM + d];
    u32 hi, lo;
    split2(w0, w1, hi, lo);
    g_WTh[idx] = hi;
    g_WTl[idx] = lo;
}

__global__ void k_rowdot(const float* __restrict__ x) {
    int row  = blockIdx.x * 8 + (threadIdx.x >> 5);
    int lane = threadIdx.x & 31;
    int s = row & (SEQ - 1);
    const float4* xr = (const float4*)(x + (size_t)row * HDIM);
    const float4* pe = (const float4*)(g_PE + (size_t)s * HDIM);
    const float4* wv = (const float4*)g_wvf;
    float4 xv = xr[lane], pv = pe[lane], wf = wv[lane];
    float acc = (xv.x + pv.x) * wf.x + (xv.y + pv.y) * wf.y +
                (xv.z + pv.z) * wf.z + (xv.w + pv.w) * wf.w;
#pragma unroll
    for (int off = 16; off; off >>= 1) acc += __shfl_xor_sync(0xFFFFFFFFu, acc, off);
    if (lane == 0) g_w[row] = acc;
}

// ======================= projection via MMA -> bf16 hi/lo Q,K =======================
// Block = 128 s-rows x 128 outputs (warps 0-3: Q cols, 4-7: K cols), K-dim 128 (2 halves of 4 ks).
// A = xp bf16 hi/lo in 4 swizzled 16KB tiles: [khalf][hi/lo], each 128 rows x 64 h (128B rows).
// B = g_WTh/g_WTl per-thread fragments (same mapping as k_scores K-frags).
__global__ void __launch_bounds__(256, 2) k_proj(const float* __restrict__ x) {
    extern __shared__ u32 smu[];
    u32 smb = smem_u32(smu);
    int tid = threadIdx.x, lane = tid & 31, w = tid >> 5;
    int b = blockIdx.y, s0 = blockIdx.x * 128;

    // fill xp tiles: split(x+PE) -> (khalf, hi/lo) tiles, swizzled
    for (int i = tid; i < 8192; i += 256) {
        int row = i >> 6, hp = i & 63;            // h-pair 0..63
        int t = hp >> 5, hpl = hp & 31;           // khalf, local pair
        const float* xr = x + (size_t)(b * SEQ + s0 + row) * HDIM + hp * 2;
        const float* pe = g_PE + (size_t)(s0 + row) * HDIM + hp * 2;
        float2 xv = *(const float2*)xr;
        float2 pv = *(const float2*)pe;
        u32 hi, lo;
        split2(xv.x + pv.x, xv.y + pv.y, hi, lo);
        int off = row * 32 + ((((hpl >> 2) ^ (row & 7))) << 2) + (hpl & 3);
        smu[t * 8192 + off]        = hi;   // AH[t]
        smu[t * 8192 + 4096 + off] = lo;   // AL[t]
    }
    __syncthreads();

    float D[8][2][4];
#pragma unroll
    for (int m = 0; m < 8; m++)
#pragma unroll
        for (int nt = 0; nt < 2; nt++)
#pragma unroll
            for (int j = 0; j < 4; j++) D[m][nt][j] = 0.f;

    u32 rbase = (u32)((lane & 15) * 128);
    u32 rx    = (u32)(lane & 7);
    u32 cadd  = (u32)(lane >> 4);

#pragma unroll
    for (int kh = 0; kh < 2; kh++) {
        // B fragments for this k-half: 2 nt x 4 ks x 2 regs, hi+lo
        u32 Bh[2][4][2], Bl[2][4][2];
#pragma unroll
        for (int nt = 0; nt < 2; nt++) {
            int n = w * 16 + nt * 8 + (lane >> 2);
#pragma unroll
            for (int ks = 0; ks < 4; ks++) {
                int base = n * 64 + (kh * 4 + ks) * 8 + (lane & 3);
                Bh[nt][ks][0] = g_WTh[base];
                Bh[nt][ks][1] = g_WTh[base + 4];
                Bl[nt][ks][0] = g_WTl[base];
                Bl[nt][ks][1] = g_WTl[base + 4];
            }
        }
        u32 tb = smb + (u32)(kh * 32768);
#pragma unroll
        for (int m = 0; m < 8; m++) {
            u32 abase = tb + (u32)(m * 2048) + rbase;
#pragma unroll
            for (int ks = 0; ks < 4; ks++) {
                u32 a = abase + ((((u32)(ks * 2) + cadd) ^ rx) << 4);
                u32 Ah[4], Al[4];
                ldm4(Ah, a);
                ldm4(Al, a + 16384);
#pragma unroll
                for (int nt = 0; nt < 2; nt++) {
                    mma16816(D[m][nt], Ah, Bh[nt][ks]);
                    mma16816(D[m][nt], Ah, Bl[nt][ks]);
                    mma16816(D[m][nt], Al, Bh[nt][ks]);
                }
            }
        }
    }

    // epilogue: scale (Q only), split to bf16 hi/lo, store [b][s][d-pair]
    bool isQ = (w < 4);
    float scale = isQ ? 0.125f : 1.0f;
    u32* dsth = isQ ? g_Qh : g_Kh;
    u32* dstl = isQ ? g_Ql : g_Kl;
    int wl = w & 3;
#pragma unroll
    for (int m = 0; m < 8; m++) {
        int row = s0 + m * 16 + (lane >> 2);
        size_t ro = ((size_t)(b * SEQ) + row) * 32;
#pragma unroll
        for (int nt = 0; nt < 2; nt++) {
            int dp = wl * 8 + nt * 4 + (lane & 3);
            u32 hi, lo;
            split2(scale * D[m][nt][0], scale * D[m][nt][1], hi, lo);
            dsth[ro + dp] = hi;
            dstl[ro + dp] = lo;
            split2(scale * D[m][nt][2], scale * D[m][nt][3], hi, lo);
            dsth[ro + 8 * 32 + dp] = hi;
            dstl[ro + 8 * 32 + dp] = lo;
        }
    }
}

// ======================= HMMA scores (ldmatrix + cp.async double-buffer) =======================
// smem: QBuf0 (Qh 16K | Ql 16K) | QBuf1 (32K) | Stg (32K)  = 96 KB
#define QBUF   32768
#define QL_OFF 16384
#define STG_U32 16384   // Stg starts at u32 index 16384 (byte 65536)

__device__ __forceinline__ void fill_async(u32 dst, int b, int q0, int tid) {
    const uint4* sH = (const uint4*)g_Qh + (size_t)(b * SEQ + q0) * 8;
    const uint4* sL = (const uint4*)g_Ql + (size_t)(b * SEQ + q0) * 8;
#pragma unroll
    for (int it = 0; it < 4; it++) {
        int i = it * 256 + tid;
        int row = i >> 3, u = i & 7;
        u32 d = (u32)(((row << 3) + (u ^ (row & 7))) << 4);
        cpa16(dst + d, sH + i);
        cpa16(dst + QL_OFF + d, sL + i);
    }
}

__global__ void __launch_bounds__(256, 2) k_scores(void) {
    extern __shared__ u32 smu[];
    u32 smb = smem_u32(smu);
    u32* Stg = smu + STG_U32;

    int tid = threadIdx.x, lane = tid & 31, w = tid >> 5;
    int b = blockIdx.y, k0 = blockIdx.x * 128;

    // resident B (K) fragments: warp's 16 k-cols, 4 k-steps, hi+lo
    u32 Bh[2][4][2], Bl[2][4][2];
#pragma unroll
    for (int nt = 0; nt < 2; nt++) {
        int rowg = b * SEQ + k0 + w * 16 + nt * 8 + (lane >> 2);
        int base = rowg * 32;
#pragma unroll
        for (int ks = 0; ks < 4; ks++) {
            Bh[nt][ks][0] = g_Kh[base + 8 * ks + (lane & 3)];
            Bh[nt][ks][1] = g_Kh[base + 8 * ks + 4 + (lane & 3)];
            Bl[nt][ks][0] = g_Kl[base + 8 * ks + (lane & 3)];
            Bl[nt][ks][1] = g_Kl[base + 8 * ks + 4 + (lane & 3)];
        }
    }

    // prefetch q-tile 0
    fill_async(smb, b, 0, tid);
    CP_COMMIT();

    float2 csum[2];
    csum[0] = make_float2(0.f, 0.f);
    csum[1] = make_float2(0.f, 0.f);

    u32 rbase = (u32)((lane & 15) * 128);
    u32 rx    = (u32)(lane & 7);
    u32 cadd  = (u32)(lane >> 4);

    for (int qi = 0; qi < 16; qi++) {
        int q0 = qi * 128;
        if (qi < 15) {
            fill_async(smb + (u32)(((qi + 1) & 1) * QBUF), b, q0 + 128, tid);
            CP_COMMIT();
            CP_WAIT(1);
        } else {
            CP_WAIT(0);
        }
        __syncthreads();   // current buffer visible; prev Stg fully drained

        u32 qb = smb + (u32)((qi & 1) * QBUF);

        float D[8][2][4];
#pragma unroll
        for (int m = 0; m < 8; m++)
#pragma unroll
            for (int nt = 0; nt < 2; nt++)
#pragma unroll
                for (int j = 0; j < 4; j++) D[m][nt][j] = 0.f;

#pragma unroll
        for (int m = 0; m < 8; m++) {
            u32 abase = qb + (u32)(m * 2048) + rbase;
#pragma unroll
            for (int ks = 0; ks < 4; ks++) {
                u32 a = abase + ((((u32)(ks * 2) + cadd) ^ rx) << 4);
                u32 Ah[4], Al[4];
                ldm4(Ah, a);
                ldm4(Al, a + QL_OFF);
#pragma unroll
                for (int nt = 0; nt < 2; nt++) {
                    mma16816(D[m][nt], Ah, Bh[nt][ks]);
                    mma16816(D[m][nt], Ah, Bl[nt][ks]);
                    mma16816(D[m][nt], Al, Bh[nt][ks]);
                }
            }
        }

        // epilogue: exp(s-8) -> fp16, stage swizzled, accumulate Z from rounded values
#pragma unroll
        for (int m = 0; m < 8; m++) {
            int rloc = m * 16 + (lane >> 2);
            int sw = (rloc & 7) << 2;
#pragma unroll
            for (int nt = 0; nt < 2; nt++) {
                int wd = w * 8 + nt * 4 + (lane & 3);
                __half2 h2 = __floats2half2_rn(__expf(D[m][nt][0] - 8.f),
                                               __expf(D[m][nt][1] - 8.f));
                *(__half2*)&Stg[rloc * 64 + (wd ^ sw)] = h2;
                float2 f = __half22float2(h2);
                csum[nt].x += f.x; csum[nt].y += f.y;

                h2 = __floats2half2_rn(__expf(D[m][nt][2] - 8.f),
                                       __expf(D[m][nt][3] - 8.f));
                *(__half2*)&Stg[(rloc + 8) * 64 + (wd ^ sw)] = h2;
                f = __half22float2(h2);
                csum[nt].x += f.x; csum[nt].y += f.y;
            }
        }
        __syncthreads();

        // coalesced store of the 128x128 fp16 tile
        const uint4* St4 = (const uint4*)Stg;
#pragma unroll
        for (int it = 0; it < 8; it++) {
            int row = it * 16 + (tid >> 4);
            int u = tid & 15;
            uint4 v = St4[row * 16 + (u ^ (row & 7))];
            *(uint4*)(g_Eh + (size_t)(b * SEQ + q0 + row) * SEQ + k0 + u * 8) = v;
        }
    }

    // Z: reduce column sums across row-groups
#pragma unroll
    for (int off = 4; off <= 16; off <<= 1) {
#pragma unroll
        for (int nt = 0; nt < 2; nt++) {
            csum[nt].x += __shfl_xor_sync(0xFFFFFFFFu, csum[nt].x, off);
            csum[nt].y += __shfl_xor_sync(0xFFFFFFFFu, csum[nt].y, off);
        }
    }
    if (lane < 4) {
#pragma unroll
        for (int nt = 0; nt < 2; nt++) {
            int idx = b * SEQ + k0 + w * 16 + nt * 8 + lane * 2;
            g_Z[idx]     = csum[nt].x;
            g_Z[idx + 1] = csum[nt].y;
        }
    }
}

// ======================= out[b,q] = bf + E[b,q,:] . (w/Z) =======================
__global__ void __launch_bounds__(256) k_out(const float* __restrict__ bf,
                                             float* __restrict__ out) {
    __shared__ float cs[SEQ];
    int b = blockIdx.y, q0 = blockIdx.x * 8;
    int tid = threadIdx.x;
    for (int i = tid; i < SEQ; i += 256)
        cs[i] = g_w[b * SEQ + i] / g_Z[b * SEQ + i];
    __syncthreads();
    int w = tid >> 5, lane = tid & 31;
    int q = q0 + w;
    const uint4* E4 = (const uint4*)(g_Eh + (size_t)(b * SEQ + q) * SEQ);
    float acc = 0.f;
#pragma unroll 2
    for (int i = lane; i < 256; i += 32) {
        uint4 v = E4[i];
        int base = i * 8;
        float4 c0 = *(const float4*)&cs[base];
        float4 c1 = *(const float4*)&cs[base + 4];
        float2 f;
        f = __half22float2(*(__half2*)&v.x); acc += f.x * c0.x + f.y * c0.y;
        f = __half22float2(*(__half2*)&v.y); acc += f.x * c0.z + f.y * c0.w;
        f = __half22float2(*(__half2*)&v.z); acc += f.x * c1.x + f.y * c1.y;
        f = __half22float2(*(__half2*)&v.w); acc += f.x * c1.z + f.y * c1.w;
    }
#pragma unroll
    for (int off = 16; off; off >>= 1) acc += __shfl_xor_sync(0xFFFFFFFFu, acc, off);
    if (lane == 0) out[b * SEQ + q] = acc + bf[0];
}

// ======================= launch =======================
extern "C" void kernel_launch(void* const* d_in, const int* in_sizes, int n_in,
                              void* d_out, int out_size) {
    const float* x  = (const float*)d_in[0];
    const float* Wq = (const float*)d_in[1];
    const float* Wk = (const float*)d_in[2];
    const float* Wv = (const float*)d_in[3];
    const float* Wf = (const float*)d_in[4];
    const float* bf = (const float*)d_in[5];
    float* out = (float*)d_out;

    cudaFuncSetAttribute(k_proj,   cudaFuncAttributeMaxDynamicSharedMemorySize, 65536);
    cudaFuncSetAttribute(k_scores, cudaFuncAttributeMaxDynamicSharedMemorySize, 98304);

    k_pe<<<(SEQ * HDIM + 255) / 256, 256>>>();
    k_wvf<<<1, 128>>>(Wv, Wf);
    k_wsplit<<<32, 256>>>(Wq, Wk);
    k_rowdot<<<(BATCH * SEQ) / 8, 256>>>(x);
    k_proj<<<dim3(SEQ / 128, BATCH), 256, 65536>>>(x);
    k_scores<<<dim3(16, BATCH), 256, 98304>>>();
    k_out<<<dim3(SEQ / 8, BATCH), 256>>>(bf, out);
}

// round 16
// speedup vs baseline: 1.9467x; 1.1046x over previous
#include <cuda_runtime.h>
#include <cuda_bf16.h>
#include <cuda_fp16.h>
#include <math.h>
#include <stdint.h>

#define BATCH 16
#define SEQ   2048
#define HDIM  128
#define DDIM  64

typedef unsigned long long u64;
typedef unsigned int u32;

// ======================= small helpers =======================
// split (x,y) into packed bf16x2 hi and lo words (low half = x)
__device__ __forceinline__ void split2(float x, float y, u32& hi, u32& lo) {
    __nv_bfloat16 hx = __float2bfloat16(x);
    __nv_bfloat16 hy = __float2bfloat16(y);
    __nv_bfloat16 lx = __float2bfloat16(x - __bfloat162float(hx));
    __nv_bfloat16 ly = __float2bfloat16(y - __bfloat162float(hy));
    hi = ((u32)__bfloat16_as_ushort(hy) << 16) | (u32)__bfloat16_as_ushort(hx);
    lo = ((u32)__bfloat16_as_ushort(ly) << 16) | (u32)__bfloat16_as_ushort(lx);
}
// split (x,y) into packed fp16x2 hi and lo words (low half = x)
__device__ __forceinline__ void split2h(float x, float y, u32& hi, u32& lo) {
    __half hx = __float2half_rn(x);
    __half hy = __float2half_rn(y);
    __half lx = __float2half_rn(x - __half2float(hx));
    __half ly = __float2half_rn(y - __half2float(hy));
    hi = ((u32)__half_as_ushort(hy) << 16) | (u32)__half_as_ushort(hx);
    lo = ((u32)__half_as_ushort(ly) << 16) | (u32)__half_as_ushort(lx);
}

// m16n8k16 bf16 MMA, fp32 accumulate in place (non-arch-suffixed)
__device__ __forceinline__ void mma16816(float* d, const u32* a, const u32* b) {
    asm volatile(
        "mma.sync.aligned.m16n8k16.row.col.f32.bf16.bf16.f32 "
        "{%0,%1,%2,%3}, {%4,%5,%6,%7}, {%8,%9}, {%0,%1,%2,%3};"
        : "+f"(d[0]), "+f"(d[1]), "+f"(d[2]), "+f"(d[3])
        : "r"(a[0]), "r"(a[1]), "r"(a[2]), "r"(a[3]), "r"(b[0]), "r"(b[1]));
}
// m16n8k16 fp16 MMA, fp32 accumulate in place (non-arch-suffixed)
__device__ __forceinline__ void mma16816h(float* d, const u32* a, const u32* b) {
    asm volatile(
        "mma.sync.aligned.m16n8k16.row.col.f32.f16.f16.f32 "
        "{%0,%1,%2,%3}, {%4,%5,%6,%7}, {%8,%9}, {%0,%1,%2,%3};"
        : "+f"(d[0]), "+f"(d[1]), "+f"(d[2]), "+f"(d[3])
        : "r"(a[0]), "r"(a[1]), "r"(a[2]), "r"(a[3]), "r"(b[0]), "r"(b[1]));
}
// ldmatrix x4 (sm_75+)
__device__ __forceinline__ void ldm4(u32* r, u32 addr) {
    asm volatile("ldmatrix.sync.aligned.m8n8.x4.shared.b16 {%0,%1,%2,%3}, [%4];"
                 : "=r"(r[0]), "=r"(r[1]), "=r"(r[2]), "=r"(r[3]) : "r"(addr));
}
// cp.async 16B (sm_80+)
__device__ __forceinline__ void cpa16(u32 dst, const void* src) {
    asm volatile("cp.async.cg.shared.global [%0], [%1], 16;" :: "r"(dst), "l"(src));
}
#define CP_COMMIT() asm volatile("cp.async.commit_group;" ::: "memory")
#define CP_WAIT(n)  asm volatile("cp.async.wait_group %0;" :: "n"(n) : "memory")

__device__ __forceinline__ u32 smem_u32(const void* p) {
    u32 a;
    asm("{ .reg .u64 t; cvta.to.shared.u64 t, %1; cvt.u32.u64 %0, t; }" : "=r"(a) : "l"(p));
    return a;
}

// ======================= device scratch =======================
__device__ u32    g_Qh[BATCH * SEQ * DDIM / 2];  // fp16x2 [b][s][d-pair], Q pre-scaled 1/8 (hi only)
__device__ u32    g_Kh[BATCH * SEQ * DDIM / 2];  // fp16x2 hi
__device__ u32    g_Kl[BATCH * SEQ * DDIM / 2];  // fp16x2 lo
__device__ __half g_Eh[(size_t)BATCH * SEQ * SEQ];  // exp(score-8), fp16, 128 MB
__device__ float  g_PE[SEQ * HDIM];
__device__ float  g_w[BATCH * SEQ];
__device__ float  g_Z[BATCH * SEQ];
__device__ float  g_wvf[HDIM];
__device__ u32    g_WTh[128 * 64];   // transposed+split weights (bf16): [n][h-pair]
__device__ u32    g_WTl[128 * 64];   // n<64: Wq col n; n>=64: Wk col n-64

// ======================= PE table =======================
__global__ void k_pe() {
    int idx = blockIdx.x * 256 + threadIdx.x;
    if (idx >= SEQ * HDIM) return;
    int s = idx / HDIM, h = idx % HDIM;
    double denom = pow(10000.0, (double)(h & ~1) / 128.0);
    float ang = (float)((double)s / denom);
    g_PE[idx] = (h & 1) ? cosf(ang) : sinf(ang);
}

__global__ void k_wvf(const float* __restrict__ Wv, const float* __restrict__ Wf) {
    int h = threadIdx.x;
    float acc = 0.f;
#pragma unroll 16
    for (int d = 0; d < DDIM; d++) acc += Wv[h * DDIM + d] * Wf[d];
    g_wvf[h] = acc;
}

// transpose + bf16-split the weights into B-fragment-friendly layout
__global__ void k_wsplit(const float* __restrict__ Wq, const float* __restrict__ Wk) {
    int idx = blockIdx.x * 256 + threadIdx.x;   // 128 n * 64 h-pairs
    if (idx >= 128 * 64) return;
    int n = idx >> 6, hp = idx & 63;
    const float* W = (n < 64) ? Wq : Wk;
    int d = n & 63;
    float w0 = W[(hp * 2) * DDIM + d];
    float w1 = W[(hp * 2 + 1) * DDIM + d];
    u32 hi, lo;
    split2(w0, w1, hi, lo);
    g_WTh[idx] = hi;
    g_WTl[idx] = lo;
}

__global__ void k_rowdot(const float* __restrict__ x) {
    int row  = blockIdx.x * 8 + (threadIdx.x >> 5);
    int lane = threadIdx.x & 31;
    int s = row & (SEQ - 1);
    const float4* xr = (const float4*)(x + (size_t)row * HDIM);
    const float4* pe = (const float4*)(g_PE + (size_t)s * HDIM);
    const float4* wv = (const float4*)g_wvf;
    float4 xv = xr[lane], pv = pe[lane], wf = wv[lane];
    float acc = (xv.x + pv.x) * wf.x + (xv.y + pv.y) * wf.y +
                (xv.z + pv.z) * wf.z + (xv.w + pv.w) * wf.w;
#pragma unroll
    for (int off = 16; off; off >>= 1) acc += __shfl_xor_sync(0xFFFFFFFFu, acc, off);
    if (lane == 0) g_w[row] = acc;
}

// ======================= projection via MMA -> fp16 Q (hi), K (hi/lo) =======================
__global__ void __launch_bounds__(256, 2) k_proj(const float* __restrict__ x) {
    extern __shared__ u32 smu[];
    u32 smb = smem_u32(smu);
    int tid = threadIdx.x, lane = tid & 31, w = tid >> 5;
    int b = blockIdx.y, s0 = blockIdx.x * 128;

    // fill xp tiles: split(x+PE) -> (khalf, hi/lo) bf16 tiles, swizzled
    for (int i = tid; i < 8192; i += 256) {
        int row = i >> 6, hp = i & 63;
        int t = hp >> 5, hpl = hp & 31;
        const float* xr = x + (size_t)(b * SEQ + s0 + row) * HDIM + hp * 2;
        const float* pe = g_PE + (size_t)(s0 + row) * HDIM + hp * 2;
        float2 xv = *(const float2*)xr;
        float2 pv = *(const float2*)pe;
        u32 hi, lo;
        split2(xv.x + pv.x, xv.y + pv.y, hi, lo);
        int off = row * 32 + ((((hpl >> 2) ^ (row & 7))) << 2) + (hpl & 3);
        smu[t * 8192 + off]        = hi;
        smu[t * 8192 + 4096 + off] = lo;
    }
    __syncthreads();

    float D[8][2][4];
#pragma unroll
    for (int m = 0; m < 8; m++)
#pragma unroll
        for (int nt = 0; nt < 2; nt++)
#pragma unroll
            for (int j = 0; j < 4; j++) D[m][nt][j] = 0.f;

    u32 rbase = (u32)((lane & 15) * 128);
    u32 rx    = (u32)(lane & 7);
    u32 cadd  = (u32)(lane >> 4);

#pragma unroll
    for (int kh = 0; kh < 2; kh++) {
        u32 Bh[2][4][2], Bl[2][4][2];
#pragma unroll
        for (int nt = 0; nt < 2; nt++) {
            int n = w * 16 + nt * 8 + (lane >> 2);
#pragma unroll
            for (int ks = 0; ks < 4; ks++) {
                int base = n * 64 + (kh * 4 + ks) * 8 + (lane & 3);
                Bh[nt][ks][0] = g_WTh[base];
                Bh[nt][ks][1] = g_WTh[base + 4];
                Bl[nt][ks][0] = g_WTl[base];
                Bl[nt][ks][1] = g_WTl[base + 4];
            }
        }
        u32 tb = smb + (u32)(kh * 32768);
#pragma unroll
        for (int m = 0; m < 8; m++) {
            u32 abase = tb + (u32)(m * 2048) + rbase;
#pragma unroll
            for (int ks = 0; ks < 4; ks++) {
                u32 a = abase + ((((u32)(ks * 2) + cadd) ^ rx) << 4);
                u32 Ah[4], Al[4];
                ldm4(Ah, a);
                ldm4(Al, a + 16384);
#pragma unroll
                for (int nt = 0; nt < 2; nt++) {
                    mma16816(D[m][nt], Ah, Bh[nt][ks]);
                    mma16816(D[m][nt], Ah, Bl[nt][ks]);
                    mma16816(D[m][nt], Al, Bh[nt][ks]);
                }
            }
        }
    }

    // epilogue: Q warps -> fp16 hi only (scaled 1/8); K warps -> fp16 hi/lo split
    bool isQ = (w < 4);
    int wl = w & 3;
#pragma unroll
    for (int m = 0; m < 8; m++) {
        int row = s0 + m * 16 + (lane >> 2);
        size_t ro = ((size_t)(b * SEQ) + row) * 32;
#pragma unroll
        for (int nt = 0; nt < 2; nt++) {
            int dp = wl * 8 + nt * 4 + (lane & 3);
            if (isQ) {
                __half2 q0 = __floats2half2_rn(.125f * D[m][nt][0], .125f * D[m][nt][1]);
                __half2 q1 = __floats2half2_rn(.125f * D[m][nt][2], .125f * D[m][nt][3]);
                g_Qh[ro + dp]          = *(u32*)&q0;
                g_Qh[ro + 8 * 32 + dp] = *(u32*)&q1;
            } else {
                u32 hi, lo;
                split2h(D[m][nt][0], D[m][nt][1], hi, lo);
                g_Kh[ro + dp] = hi;
                g_Kl[ro + dp] = lo;
                split2h(D[m][nt][2], D[m][nt][3], hi, lo);
                g_Kh[ro + 8 * 32 + dp] = hi;
                g_Kl[ro + 8 * 32 + dp] = lo;
            }
        }
    }
}

// ======================= HMMA scores (fp16 2-term, Q hi only) =======================
// smem: QBuf0 16K | QBuf1 16K | Stg 32K  = 64 KB
#define QBUF    16384
#define STG_U32 8192    // Stg starts at u32 index 8192 (byte 32768)

__device__ __forceinline__ void fill_async(u32 dst, int b, int q0, int tid) {
    const uint4* sH = (const uint4*)g_Qh + (size_t)(b * SEQ + q0) * 8;
#pragma unroll
    for (int it = 0; it < 4; it++) {
        int i = it * 256 + tid;
        int row = i >> 3, u = i & 7;
        u32 d = (u32)(((row << 3) + (u ^ (row & 7))) << 4);
        cpa16(dst + d, sH + i);
    }
}

__global__ void __launch_bounds__(256, 2) k_scores(void) {
    extern __shared__ u32 smu[];
    u32 smb = smem_u32(smu);
    u32* Stg = smu + STG_U32;

    int tid = threadIdx.x, lane = tid & 31, w = tid >> 5;
    int b = blockIdx.y, k0 = blockIdx.x * 128;

    // resident B (K) fragments: warp's 16 k-cols, 4 k-steps, fp16 hi+lo
    u32 Bh[2][4][2], Bl[2][4][2];
#pragma unroll
    for (int nt = 0; nt < 2; nt++) {
        int rowg = b * SEQ + k0 + w * 16 + nt * 8 + (lane >> 2);
        int base = rowg * 32;
#pragma unroll
        for (int ks = 0; ks < 4; ks++) {
            Bh[nt][ks][0] = g_Kh[base + 8 * ks + (lane & 3)];
            Bh[nt][ks][1] = g_Kh[base + 8 * ks + 4 + (lane & 3)];
            Bl[nt][ks][0] = g_Kl[base + 8 * ks + (lane & 3)];
            Bl[nt][ks][1] = g_Kl[base + 8 * ks + 4 + (lane & 3)];
        }
    }

    fill_async(smb, b, 0, tid);
    CP_COMMIT();

    float2 csum[2];
    csum[0] = make_float2(0.f, 0.f);
    csum[1] = make_float2(0.f, 0.f);

    u32 rbase = (u32)((lane & 15) * 128);
    u32 rx    = (u32)(lane & 7);
    u32 cadd  = (u32)(lane >> 4);

    for (int qi = 0; qi < 16; qi++) {
        int q0 = qi * 128;
        if (qi < 15) {
            fill_async(smb + (u32)(((qi + 1) & 1) * QBUF), b, q0 + 128, tid);
            CP_COMMIT();
            CP_WAIT(1);
        } else {
            CP_WAIT(0);
        }
        __syncthreads();

        u32 qb = smb + (u32)((qi & 1) * QBUF);

        float D[8][2][4];
#pragma unroll
        for (int m = 0; m < 8; m++)
#pragma unroll
            for (int nt = 0; nt < 2; nt++)
#pragma unroll
                for (int j = 0; j < 4; j++) D[m][nt][j] = 0.f;

#pragma unroll
        for (int m = 0; m < 8; m++) {
            u32 abase = qb + (u32)(m * 2048) + rbase;
#pragma unroll
            for (int ks = 0; ks < 4; ks++) {
                u32 a = abase + ((((u32)(ks * 2) + cadd) ^ rx) << 4);
                u32 Ah[4];
                ldm4(Ah, a);
#pragma unroll
                for (int nt = 0; nt < 2; nt++) {
                    mma16816h(D[m][nt], Ah, Bh[nt][ks]);
                    mma16816h(D[m][nt], Ah, Bl[nt][ks]);
                }
            }
        }

        // epilogue: exp(s-8) -> fp16, stage swizzled, accumulate Z from rounded values
#pragma unroll
        for (int m = 0; m < 8; m++) {
            int rloc = m * 16 + (lane >> 2);
            int sw = (rloc & 7) << 2;
#pragma unroll
            for (int nt = 0; nt < 2; nt++) {
                int wd = w * 8 + nt * 4 + (lane & 3);
                __half2 h2 = __floats2half2_rn(__expf(D[m][nt][0] - 8.f),
                                               __expf(D[m][nt][1] - 8.f));
                *(__half2*)&Stg[rloc * 64 + (wd ^ sw)] = h2;
                float2 f = __half22float2(h2);
                csum[nt].x += f.x; csum[nt].y += f.y;

                h2 = __floats2half2_rn(__expf(D[m][nt][2] - 8.f),
                                       __expf(D[m][nt][3] - 8.f));
                *(__half2*)&Stg[(rloc + 8) * 64 + (wd ^ sw)] = h2;
                f = __half22float2(h2);
                csum[nt].x += f.x; csum[nt].y += f.y;
            }
        }
        __syncthreads();

        // coalesced store of the 128x128 fp16 tile
        const uint4* St4 = (const uint4*)Stg;
#pragma unroll
        for (int it = 0; it < 8; it++) {
            int row = it * 16 + (tid >> 4);
            int u = tid & 15;
            uint4 v = St4[row * 16 + (u ^ (row & 7))];
            *(uint4*)(g_Eh + (size_t)(b * SEQ + q0 + row) * SEQ + k0 + u * 8) = v;
        }
    }

    // Z: reduce column sums across row-groups
#pragma unroll
    for (int off = 4; off <= 16; off <<= 1) {
#pragma unroll
        for (int nt = 0; nt < 2; nt++) {
            csum[nt].x += __shfl_xor_sync(0xFFFFFFFFu, csum[nt].x, off);
            csum[nt].y += __shfl_xor_sync(0xFFFFFFFFu, csum[nt].y, off);
        }
    }
    if (lane < 4) {
#pragma unroll
        for (int nt = 0; nt < 2; nt++) {
            int idx = b * SEQ + k0 + w * 16 + nt * 8 + lane * 2;
            g_Z[idx]     = csum[nt].x;
            g_Z[idx + 1] = csum[nt].y;
        }
    }
}

// ======================= out[b,q] = bf + E[b,q,:] . (w/Z) =======================
__global__ void __launch_bounds__(256) k_out(const float* __restrict__ bf,
                                             float* __restrict__ out) {
    __shared__ float cs[SEQ];
    int b = blockIdx.y, q0 = blockIdx.x * 8;
    int tid = threadIdx.x;
    for (int i = tid; i < SEQ; i += 256)
        cs[i] = g_w[b * SEQ + i] / g_Z[b * SEQ + i];
    __syncthreads();
    int w = tid >> 5, lane = tid & 31;
    int q = q0 + w;
    const uint4* E4 = (const uint4*)(g_Eh + (size_t)(b * SEQ + q) * SEQ);
    float acc = 0.f;
#pragma unroll 2
    for (int i = lane; i < 256; i += 32) {
        uint4 v = E4[i];
        int base = i * 8;
        float4 c0 = *(const float4*)&cs[base];
        float4 c1 = *(const float4*)&cs[base + 4];
        float2 f;
        f = __half22float2(*(__half2*)&v.x); acc += f.x * c0.x + f.y * c0.y;
        f = __half22float2(*(__half2*)&v.y); acc += f.x * c0.z + f.y * c0.w;
        f = __half22float2(*(__half2*)&v.z); acc += f.x * c1.x + f.y * c1.y;
        f = __half22float2(*(__half2*)&v.w); acc += f.x * c1.z + f.y * c1.w;
    }
#pragma unroll
    for (int off = 16; off; off >>= 1) acc += __shfl_xor_sync(0xFFFFFFFFu, acc, off);
    if (lane == 0) out[b * SEQ + q] = acc + bf[0];
}

// ======================= launch =======================
extern "C" void kernel_launch(void* const* d_in, const int* in_sizes, int n_in,
                              void* d_out, int out_size) {
    const float* x  = (const float*)d_in[0];
    const float* Wq = (const float*)d_in[1];
    const float* Wk = (const float*)d_in[2];
    const float* Wv = (const float*)d_in[3];
    const float* Wf = (const float*)d_in[4];
    const float* bf = (const float*)d_in[5];
    float* out = (float*)d_out;

    cudaFuncSetAttribute(k_proj,   cudaFuncAttributeMaxDynamicSharedMemorySize, 65536);
    cudaFuncSetAttribute(k_scores, cudaFuncAttributeMaxDynamicSharedMemorySize, 65536);

    k_pe<<<(SEQ * HDIM + 255) / 256, 256>>>();
    k_wvf<<<1, 128>>>(Wv, Wf);
    k_wsplit<<<32, 256>>>(Wq, Wk);
    k_rowdot<<<(BATCH * SEQ) / 8, 256>>>(x);
    k_proj<<<dim3(SEQ / 128, BATCH), 256, 65536>>>(x);
    k_scores<<<dim3(16, BATCH), 256, 65536>>>();
    k_out<<<dim3(SEQ / 8, BATCH), 256>>>(bf, out);
}

// round 17
// speedup vs baseline: 2.1965x; 1.1283x over previous
#include <cuda_runtime.h>
#include <cuda_bf16.h>
#include <cuda_fp16.h>
#include <math.h>
#include <stdint.h>

#define BATCH 16
#define SEQ   2048
#define HDIM  128
#define DDIM  64

typedef unsigned long long u64;
typedef unsigned int u32;

// ======================= small helpers =======================
// split (x,y) into packed bf16x2 hi and lo words (low half = x)
__device__ __forceinline__ void split2(float x, float y, u32& hi, u32& lo) {
    __nv_bfloat16 hx = __float2bfloat16(x);
    __nv_bfloat16 hy = __float2bfloat16(y);
    __nv_bfloat16 lx = __float2bfloat16(x - __bfloat162float(hx));
    __nv_bfloat16 ly = __float2bfloat16(y - __bfloat162float(hy));
    hi = ((u32)__bfloat16_as_ushort(hy) << 16) | (u32)__bfloat16_as_ushort(hx);
    lo = ((u32)__bfloat16_as_ushort(ly) << 16) | (u32)__bfloat16_as_ushort(lx);
}

// m16n8k16 bf16 MMA, fp32 accumulate in place (non-arch-suffixed)
__device__ __forceinline__ void mma16816(float* d, const u32* a, const u32* b) {
    asm volatile(
        "mma.sync.aligned.m16n8k16.row.col.f32.bf16.bf16.f32 "
        "{%0,%1,%2,%3}, {%4,%5,%6,%7}, {%8,%9}, {%0,%1,%2,%3};"
        : "+f"(d[0]), "+f"(d[1]), "+f"(d[2]), "+f"(d[3])
        : "r"(a[0]), "r"(a[1]), "r"(a[2]), "r"(a[3]), "r"(b[0]), "r"(b[1]));
}
// m16n8k16 fp16 MMA, fp32 accumulate in place (non-arch-suffixed)
__device__ __forceinline__ void mma16816h(float* d, const u32* a, const u32* b) {
    asm volatile(
        "mma.sync.aligned.m16n8k16.row.col.f32.f16.f16.f32 "
        "{%0,%1,%2,%3}, {%4,%5,%6,%7}, {%8,%9}, {%0,%1,%2,%3};"
        : "+f"(d[0]), "+f"(d[1]), "+f"(d[2]), "+f"(d[3])
        : "r"(a[0]), "r"(a[1]), "r"(a[2]), "r"(a[3]), "r"(b[0]), "r"(b[1]));
}
// ldmatrix x4 (sm_75+)
__device__ __forceinline__ void ldm4(u32* r, u32 addr) {
    asm volatile("ldmatrix.sync.aligned.m8n8.x4.shared.b16 {%0,%1,%2,%3}, [%4];"
                 : "=r"(r[0]), "=r"(r[1]), "=r"(r[2]), "=r"(r[3]) : "r"(addr));
}
// cp.async 16B (sm_80+)
__device__ __forceinline__ void cpa16(u32 dst, const void* src) {
    asm volatile("cp.async.cg.shared.global [%0], [%1], 16;" :: "r"(dst), "l"(src));
}
#define CP_COMMIT() asm volatile("cp.async.commit_group;" ::: "memory")
#define CP_WAIT(n)  asm volatile("cp.async.wait_group %0;" :: "n"(n) : "memory")

__device__ __forceinline__ u32 smem_u32(const void* p) {
    u32 a;
    asm("{ .reg .u64 t; cvta.to.shared.u64 t, %1; cvt.u32.u64 %0, t; }" : "=r"(a) : "l"(p));
    return a;
}

// ======================= device scratch =======================
__device__ u32    g_Qh[BATCH * SEQ * DDIM / 2];  // fp16x2 [b][s][d-pair], Q pre-scaled 1/8
__device__ u32    g_Kh[BATCH * SEQ * DDIM / 2];  // fp16x2
__device__ __half g_Eh[(size_t)BATCH * SEQ * SEQ];  // exp(score-8), fp16, 128 MB
__device__ float  g_PE[SEQ * HDIM];
__device__ float  g_w[BATCH * SEQ];
__device__ float  g_Z[BATCH * SEQ];
__device__ float  g_wvf[HDIM];
__device__ u32    g_WTh[128 * 64];   // transposed+split weights (bf16): [n][h-pair]
__device__ u32    g_WTl[128 * 64];   // n<64: Wq col n; n>=64: Wk col n-64

// ======================= PE table =======================
__global__ void k_pe() {
    int idx = blockIdx.x * 256 + threadIdx.x;
    if (idx >= SEQ * HDIM) return;
    int s = idx / HDIM, h = idx % HDIM;
    double denom = pow(10000.0, (double)(h & ~1) / 128.0);
    float ang = (float)((double)s / denom);
    g_PE[idx] = (h & 1) ? cosf(ang) : sinf(ang);
}

__global__ void k_wvf(const float* __restrict__ Wv, const float* __restrict__ Wf) {
    int h = threadIdx.x;
    float acc = 0.f;
#pragma unroll 16
    for (int d = 0; d < DDIM; d++) acc += Wv[h * DDIM + d] * Wf[d];
    g_wvf[h] = acc;
}

// transpose + bf16-split the weights into B-fragment-friendly layout
__global__ void k_wsplit(const float* __restrict__ Wq, const float* __restrict__ Wk) {
    int idx = blockIdx.x * 256 + threadIdx.x;   // 128 n * 64 h-pairs
    if (idx >= 128 * 64) return;
    int n = idx >> 6, hp = idx & 63;
    const float* W = (n < 64) ? Wq : Wk;
    int d = n & 63;
    float w0 = W[(hp * 2) * DDIM + d];
    float w1 = W[(hp * 2 + 1) * DDIM + d];
    u32 hi, lo;
    split2(w0, w1, hi, lo);
    g_WTh[idx] = hi;
    g_WTl[idx] = lo;
}

__global__ void k_rowdot(const float* __restrict__ x) {
    int row  = blockIdx.x * 8 + (threadIdx.x >> 5);
    int lane = threadIdx.x & 31;
    int s = row & (SEQ - 1);
    const float4* xr = (const float4*)(x + (size_t)row * HDIM);
    const float4* pe = (const float4*)(g_PE + (size_t)s * HDIM);
    const float4* wv = (const float4*)g_wvf;
    float4 xv = xr[lane], pv = pe[lane], wf = wv[lane];
    float acc = (xv.x + pv.x) * wf.x + (xv.y + pv.y) * wf.y +
                (xv.z + pv.z) * wf.z + (xv.w + pv.w) * wf.w;
#pragma unroll
    for (int off = 16; off; off >>= 1) acc += __shfl_xor_sync(0xFFFFFFFFu, acc, off);
    if (lane == 0) g_w[row] = acc;
}

// ======================= projection via MMA -> fp16 Q, K =======================
__global__ void __launch_bounds__(256, 2) k_proj(const float* __restrict__ x) {
    extern __shared__ u32 smu[];
    u32 smb = smem_u32(smu);
    int tid = threadIdx.x, lane = tid & 31, w = tid >> 5;
    int b = blockIdx.y, s0 = blockIdx.x * 128;

    // fill xp tiles: split(x+PE) -> (khalf, hi/lo) bf16 tiles, swizzled
    for (int i = tid; i < 8192; i += 256) {
        int row = i >> 6, hp = i & 63;
        int t = hp >> 5, hpl = hp & 31;
        const float* xr = x + (size_t)(b * SEQ + s0 + row) * HDIM + hp * 2;
        const float* pe = g_PE + (size_t)(s0 + row) * HDIM + hp * 2;
        float2 xv = *(const float2*)xr;
        float2 pv = *(const float2*)pe;
        u32 hi, lo;
        split2(xv.x + pv.x, xv.y + pv.y, hi, lo);
        int off = row * 32 + ((((hpl >> 2) ^ (row & 7))) << 2) + (hpl & 3);
        smu[t * 8192 + off]        = hi;
        smu[t * 8192 + 4096 + off] = lo;
    }
    __syncthreads();

    float D[8][2][4];
#pragma unroll
    for (int m = 0; m < 8; m++)
#pragma unroll
        for (int nt = 0; nt < 2; nt++)
#pragma unroll
            for (int j = 0; j < 4; j++) D[m][nt][j] = 0.f;

    u32 rbase = (u32)((lane & 15) * 128);
    u32 rx    = (u32)(lane & 7);
    u32 cadd  = (u32)(lane >> 4);

#pragma unroll
    for (int kh = 0; kh < 2; kh++) {
        u32 Bh[2][4][2], Bl[2][4][2];
#pragma unroll
        for (int nt = 0; nt < 2; nt++) {
            int n = w * 16 + nt * 8 + (lane >> 2);
#pragma unroll
            for (int ks = 0; ks < 4; ks++) {
                int base = n * 64 + (kh * 4 + ks) * 8 + (lane & 3);
                Bh[nt][ks][0] = g_WTh[base];
                Bh[nt][ks][1] = g_WTh[base + 4];
                Bl[nt][ks][0] = g_WTl[base];
                Bl[nt][ks][1] = g_WTl[base + 4];
            }
        }
        u32 tb = smb + (u32)(kh * 32768);
#pragma unroll
        for (int m = 0; m < 8; m++) {
            u32 abase = tb + (u32)(m * 2048) + rbase;
#pragma unroll
            for (int ks = 0; ks < 4; ks++) {
                u32 a = abase + ((((u32)(ks * 2) + cadd) ^ rx) << 4);
                u32 Ah[4], Al[4];
                ldm4(Ah, a);
                ldm4(Al, a + 16384);
#pragma unroll
                for (int nt = 0; nt < 2; nt++) {
                    mma16816(D[m][nt], Ah, Bh[nt][ks]);
                    mma16816(D[m][nt], Ah, Bl[nt][ks]);
                    mma16816(D[m][nt], Al, Bh[nt][ks]);
                }
            }
        }
    }

    // epilogue: fp16 round-to-nearest; Q warps scaled 1/8
    bool isQ = (w < 4);
    float scale = isQ ? 0.125f : 1.0f;
    u32* dst = isQ ? g_Qh : g_Kh;
    int wl = w & 3;
#pragma unroll
    for (int m = 0; m < 8; m++) {
        int row = s0 + m * 16 + (lane >> 2);
        size_t ro = ((size_t)(b * SEQ) + row) * 32;
#pragma unroll
        for (int nt = 0; nt < 2; nt++) {
            int dp = wl * 8 + nt * 4 + (lane & 3);
            __half2 v0 = __floats2half2_rn(scale * D[m][nt][0], scale * D[m][nt][1]);
            __half2 v1 = __floats2half2_rn(scale * D[m][nt][2], scale * D[m][nt][3]);
            dst[ro + dp]          = *(u32*)&v0;
            dst[ro + 8 * 32 + dp] = *(u32*)&v1;
        }
    }
}

// ======================= HMMA scores (fp16 single-term) =======================
// smem: QBuf0 16K | QBuf1 16K | Stg 32K  = 64 KB
#define QBUF    16384
#define STG_U32 8192    // Stg starts at u32 index 8192 (byte 32768)

__device__ __forceinline__ void fill_async(u32 dst, int b, int q0, int tid) {
    const uint4* sH = (const uint4*)g_Qh + (size_t)(b * SEQ + q0) * 8;
#pragma unroll
    for (int it = 0; it < 4; it++) {
        int i = it * 256 + tid;
        int row = i >> 3, u = i & 7;
        u32 d = (u32)(((row << 3) + (u ^ (row & 7))) << 4);
        cpa16(dst + d, sH + i);
    }
}

__global__ void __launch_bounds__(256, 2) k_scores(void) {
    extern __shared__ u32 smu[];
    u32 smb = smem_u32(smu);
    u32* Stg = smu + STG_U32;

    int tid = threadIdx.x, lane = tid & 31, w = tid >> 5;
    int b = blockIdx.y, k0 = blockIdx.x * 128;

    // resident B (K) fragments: warp's 16 k-cols, 4 k-steps, fp16
    u32 Bh[2][4][2];
#pragma unroll
    for (int nt = 0; nt < 2; nt++) {
        int rowg = b * SEQ + k0 + w * 16 + nt * 8 + (lane >> 2);
        int base = rowg * 32;
#pragma unroll
        for (int ks = 0; ks < 4; ks++) {
            Bh[nt][ks][0] = g_Kh[base + 8 * ks + (lane & 3)];
            Bh[nt][ks][1] = g_Kh[base + 8 * ks + 4 + (lane & 3)];
        }
    }

    fill_async(smb, b, 0, tid);
    CP_COMMIT();

    float2 csum[2];
    csum[0] = make_float2(0.f, 0.f);
    csum[1] = make_float2(0.f, 0.f);

    u32 rbase = (u32)((lane & 15) * 128);
    u32 rx    = (u32)(lane & 7);
    u32 cadd  = (u32)(lane >> 4);

    for (int qi = 0; qi < 16; qi++) {
        int q0 = qi * 128;
        if (qi < 15) {
            fill_async(smb + (u32)(((qi + 1) & 1) * QBUF), b, q0 + 128, tid);
            CP_COMMIT();
            CP_WAIT(1);
        } else {
            CP_WAIT(0);
        }
        __syncthreads();

        u32 qb = smb + (u32)((qi & 1) * QBUF);

        float D[8][2][4];
#pragma unroll
        for (int m = 0; m < 8; m++)
#pragma unroll
            for (int nt = 0; nt < 2; nt++)
#pragma unroll
                for (int j = 0; j < 4; j++) D[m][nt][j] = 0.f;

#pragma unroll
        for (int m = 0; m < 8; m++) {
            u32 abase = qb + (u32)(m * 2048) + rbase;
#pragma unroll
            for (int ks = 0; ks < 4; ks++) {
                u32 a = abase + ((((u32)(ks * 2) + cadd) ^ rx) << 4);
                u32 Ah[4];
                ldm4(Ah, a);
#pragma unroll
                for (int nt = 0; nt < 2; nt++)
                    mma16816h(D[m][nt], Ah, Bh[nt][ks]);
            }
        }

        // epilogue: exp(s-8) -> fp16, stage swizzled, accumulate Z from rounded values
#pragma unroll
        for (int m = 0; m < 8; m++) {
            int rloc = m * 16 + (lane >> 2);
            int sw = (rloc & 7) << 2;
#pragma unroll
            for (int nt = 0; nt < 2; nt++) {
                int wd = w * 8 + nt * 4 + (lane & 3);
                __half2 h2 = __floats2half2_rn(__expf(D[m][nt][0] - 8.f),
                                               __expf(D[m][nt][1] - 8.f));
                *(__half2*)&Stg[rloc * 64 + (wd ^ sw)] = h2;
                float2 f = __half22float2(h2);
                csum[nt].x += f.x; csum[nt].y += f.y;

                h2 = __floats2half2_rn(__expf(D[m][nt][2] - 8.f),
                                       __expf(D[m][nt][3] - 8.f));
                *(__half2*)&Stg[(rloc + 8) * 64 + (wd ^ sw)] = h2;
                f = __half22float2(h2);
                csum[nt].x += f.x; csum[nt].y += f.y;
            }
        }
        __syncthreads();

        // coalesced store of the 128x128 fp16 tile
        const uint4* St4 = (const uint4*)Stg;
#pragma unroll
        for (int it = 0; it < 8; it++) {
            int row = it * 16 + (tid >> 4);
            int u = tid & 15;
            uint4 v = St4[row * 16 + (u ^ (row & 7))];
            *(uint4*)(g_Eh + (size_t)(b * SEQ + q0 + row) * SEQ + k0 + u * 8) = v;
        }
    }

    // Z: reduce column sums across row-groups
#pragma unroll
    for (int off = 4; off <= 16; off <<= 1) {
#pragma unroll
        for (int nt = 0; nt < 2; nt++) {
            csum[nt].x += __shfl_xor_sync(0xFFFFFFFFu, csum[nt].x, off);
            csum[nt].y += __shfl_xor_sync(0xFFFFFFFFu, csum[nt].y, off);
        }
    }
    if (lane < 4) {
#pragma unroll
        for (int nt = 0; nt < 2; nt++) {
            int idx = b * SEQ + k0 + w * 16 + nt * 8 + lane * 2;
            g_Z[idx]     = csum[nt].x;
            g_Z[idx + 1] = csum[nt].y;
        }
    }
}

// ======================= out[b,q] = bf + E[b,q,:] . (w/Z) =======================
__global__ void __launch_bounds__(256) k_out(const float* __restrict__ bf,
                                             float* __restrict__ out) {
    __shared__ float cs[SEQ];
    int b = blockIdx.y, q0 = blockIdx.x * 8;
    int tid = threadIdx.x;
    for (int i = tid; i < SEQ; i += 256)
        cs[i] = g_w[b * SEQ + i] / g_Z[b * SEQ + i];
    __syncthreads();
    int w = tid >> 5, lane = tid & 31;
    int q = q0 + w;
    const uint4* E4 = (const uint4*)(g_Eh + (size_t)(b * SEQ + q) * SEQ);
    float acc = 0.f;
#pragma unroll 2
    for (int i = lane; i < 256; i += 32) {
        uint4 v = E4[i];
        int base = i * 8;
        float4 c0 = *(const float4*)&cs[base];
        float4 c1 = *(const float4*)&cs[base + 4];
        float2 f;
        f = __half22float2(*(__half2*)&v.x); acc += f.x * c0.x + f.y * c0.y;
        f = __half22float2(*(__half2*)&v.y); acc += f.x * c0.z + f.y * c0.w;
        f = __half22float2(*(__half2*)&v.z); acc += f.x * c1.x + f.y * c1.y;
        f = __half22float2(*(__half2*)&v.w); acc += f.x * c1.z + f.y * c1.w;
    }
#pragma unroll
    for (int off = 16; off; off >>= 1) acc += __shfl_xor_sync(0xFFFFFFFFu, acc, off);
    if (lane == 0) out[b * SEQ + q] = acc + bf[0];
}

// ======================= launch =======================
extern "C" void kernel_launch(void* const* d_in, const int* in_sizes, int n_in,
                              void* d_out, int out_size) {
    const float* x  = (const float*)d_in[0];
    const float* Wq = (const float*)d_in[1];
    const float* Wk = (const float*)d_in[2];
    const float* Wv = (const float*)d_in[3];
    const float* Wf = (const float*)d_in[4];
    const float* bf = (const float*)d_in[5];
    float* out = (float*)d_out;

    cudaFuncSetAttribute(k_proj,   cudaFuncAttributeMaxDynamicSharedMemorySize, 65536);
    cudaFuncSetAttribute(k_scores, cudaFuncAttributeMaxDynamicSharedMemorySize, 65536);

    k_pe<<<(SEQ * HDIM + 255) / 256, 256>>>();
    k_wvf<<<1, 128>>>(Wv, Wf);
    k_wsplit<<<32, 256>>>(Wq, Wk);
    k_rowdot<<<(BATCH * SEQ) / 8, 256>>>(x);
    k_proj<<<dim3(SEQ / 128, BATCH), 256, 65536>>>(x);
    k_scores<<<dim3(16, BATCH), 256, 65536>>>();
    k_out<<<dim3(SEQ / 8, BATCH), 256>>>(bf, out);
}